// round 1
// baseline (speedup 1.0000x reference)
#include <cuda_runtime.h>
#include <cstdint>

#define NROWS 32768
#define NFEAT 2048
#define NHID  4096
#define NCLS  512
#define RS    32          // row splits for column stats (deterministic 2-stage)

#define BM 128
#define BN 128
#define BK 16
#define TM 8
#define TN 8

// ---------------- scratch (device globals; no allocation allowed) ----------------
__device__ float  g_h1 [(size_t)NROWS * NHID];     // 512 MB activation
__device__ float  g_W1f[(size_t)NHID  * NFEAT];    // folded W1
__device__ float  g_W2f[(size_t)NCLS  * NHID];     // folded W2
__device__ float  g_b1f[NHID];
__device__ float  g_b2f[NCLS];
__device__ float  g_scale1[NFEAT], g_shift1[NFEAT];
__device__ float  g_scale2[NHID],  g_shift2[NHID];
__device__ double g_psum  [RS * NHID];
__device__ double g_psumsq[RS * NHID];

// ---------------- f32x2 helpers (Blackwell packed FFMA2) ----------------
__device__ __forceinline__ unsigned long long fma_f32x2(unsigned long long a,
                                                        unsigned long long b,
                                                        unsigned long long c) {
    unsigned long long d;
    asm("fma.rn.f32x2 %0, %1, %2, %3;" : "=l"(d) : "l"(a), "l"(b), "l"(c));
    return d;
}
__device__ __forceinline__ unsigned long long pack2(float x) {
    unsigned long long r;
    asm("mov.b64 %0, {%1, %1};" : "=l"(r) : "r"(__float_as_uint(x)));
    return r;
}
__device__ __forceinline__ void unpack2(unsigned long long v, float& lo, float& hi) {
    unsigned int l, h;
    asm("mov.b64 {%0, %1}, %2;" : "=r"(l), "=r"(h) : "l"(v));
    lo = __uint_as_float(l); hi = __uint_as_float(h);
}

// ---------------- stage A: per-column partial sums (double accumulators) ----------------
__global__ void col_stats_partial(const float* __restrict__ X, int C, int rowsPer) {
    int c  = blockIdx.x * blockDim.x + threadIdx.x;
    const float* p = X + (size_t)blockIdx.y * rowsPer * C + c;
    double s0 = 0, s1 = 0, s2 = 0, s3 = 0;
    double q0 = 0, q1 = 0, q2 = 0, q3 = 0;
    for (int r = 0; r < rowsPer; r += 4) {
        float v0 = p[(size_t)(r + 0) * C];
        float v1 = p[(size_t)(r + 1) * C];
        float v2 = p[(size_t)(r + 2) * C];
        float v3 = p[(size_t)(r + 3) * C];
        s0 += v0; q0 += (double)v0 * v0;
        s1 += v1; q1 += (double)v1 * v1;
        s2 += v2; q2 += (double)v2 * v2;
        s3 += v3; q3 += (double)v3 * v3;
    }
    g_psum  [blockIdx.y * C + c] = (s0 + s1) + (s2 + s3);
    g_psumsq[blockIdx.y * C + c] = (q0 + q1) + (q2 + q3);
}

// ---------------- stage B: finalize mean/var -> per-column scale/shift ----------------
__global__ void col_stats_finalize(const float* __restrict__ gamma,
                                   const float* __restrict__ bnb,
                                   float* __restrict__ scale,
                                   float* __restrict__ shift, int C) {
    int c = blockIdx.x * blockDim.x + threadIdx.x;
    double s = 0, q = 0;
    for (int i = 0; i < RS; i++) { s += g_psum[i * C + c]; q += g_psumsq[i * C + c]; }
    double mu  = s * (1.0 / NROWS);
    double var = q * (1.0 / NROWS) - mu * mu;
    float a = rsqrtf((float)var + 1e-5f) * gamma[c];
    scale[c] = a;
    shift[c] = bnb[c] - (float)mu * a;
}

// ---------------- fold BN affine into weights + bias (deterministic reduce) -------------
__global__ void fold_weights(const float* __restrict__ W, const float* __restrict__ bias,
                             const float* __restrict__ scale, const float* __restrict__ shift,
                             float* __restrict__ Wf, float* __restrict__ bf, int K) {
    int j = blockIdx.x;
    const float* Wr = W + (size_t)j * K;
    float* Wfr = Wf + (size_t)j * K;
    float dot = 0.f;
    for (int k = threadIdx.x; k < K; k += 256) {
        float w = Wr[k];
        Wfr[k] = w * scale[k];
        dot += w * shift[k];
    }
    __shared__ float red[256];
    red[threadIdx.x] = dot;
    __syncthreads();
    for (int s = 128; s > 0; s >>= 1) {
        if (threadIdx.x < s) red[threadIdx.x] += red[threadIdx.x + s];
        __syncthreads();
    }
    if (threadIdx.x == 0) bf[j] = bias[j] + red[0];
}

// ---------------- SGEMM: C[M,Nout] = A[M,K] @ Wf[Nout,K]^T + bias (+relu / +beta*y) -----
// 128x128 tile, BK=16, 256 threads, 8x8 per thread, f32x2 packed FMA accumulators.
template <bool RELU, bool ADDY>
__global__ __launch_bounds__(256, 2)
void gemm_bias(const float* __restrict__ A, const float* __restrict__ B,
               const float* __restrict__ bias, const float* __restrict__ Y,
               const float* __restrict__ betap, float* __restrict__ C,
               int M, int Nout, int K) {
    __shared__ __align__(16) float As[BK][BM];
    __shared__ __align__(16) float Bs[BK][BN];

    const int tid = threadIdx.x;
    const int bm  = blockIdx.y * BM;
    const int bn  = blockIdx.x * BN;

    // loaders: 2 rows of threads per tile row, 8 floats (2x float4) each
    const int lr = tid >> 1;
    const int lc = (tid & 1) * 8;
    const float* Ap = A + (size_t)(bm + lr) * K + lc;
    const float* Bp = B + (size_t)(bn + lr) * K + lc;

    const int trow = (tid >> 4) * TM;   // 0..120
    const int tcol = (tid & 15) * TN;   // 0..120

    unsigned long long acc[TM][TN / 2];
#pragma unroll
    for (int i = 0; i < TM; i++)
#pragma unroll
        for (int j = 0; j < TN / 2; j++) acc[i][j] = 0ull;

    for (int k0 = 0; k0 < K; k0 += BK) {
        float4 a0 = *(const float4*)(Ap + k0);
        float4 a1 = *(const float4*)(Ap + k0 + 4);
        float4 b0 = *(const float4*)(Bp + k0);
        float4 b1 = *(const float4*)(Bp + k0 + 4);
        As[lc + 0][lr] = a0.x; As[lc + 1][lr] = a0.y; As[lc + 2][lr] = a0.z; As[lc + 3][lr] = a0.w;
        As[lc + 4][lr] = a1.x; As[lc + 5][lr] = a1.y; As[lc + 6][lr] = a1.z; As[lc + 7][lr] = a1.w;
        Bs[lc + 0][lr] = b0.x; Bs[lc + 1][lr] = b0.y; Bs[lc + 2][lr] = b0.z; Bs[lc + 3][lr] = b0.w;
        Bs[lc + 4][lr] = b1.x; Bs[lc + 5][lr] = b1.y; Bs[lc + 6][lr] = b1.z; Bs[lc + 7][lr] = b1.w;
        __syncthreads();
#pragma unroll
        for (int kk = 0; kk < BK; kk++) {
            unsigned long long rb[TN / 2];
#pragma unroll
            for (int j = 0; j < TN / 2; j++)
                rb[j] = *(const unsigned long long*)&Bs[kk][tcol + 2 * j];
            float a8[TM];
            *(float4*)&a8[0] = *(const float4*)&As[kk][trow];
            *(float4*)&a8[4] = *(const float4*)&As[kk][trow + 4];
#pragma unroll
            for (int i = 0; i < TM; i++) {
                unsigned long long ra = pack2(a8[i]);
#pragma unroll
                for (int j = 0; j < TN / 2; j++)
                    acc[i][j] = fma_f32x2(ra, rb[j], acc[i][j]);
            }
        }
        __syncthreads();
    }

    const float bscale = ADDY ? __ldg(betap) : 0.f;
#pragma unroll
    for (int i = 0; i < TM; i++) {
        const int m = bm + trow + i;
#pragma unroll
        for (int j = 0; j < TN / 2; j++) {
            const int n = bn + tcol + 2 * j;
            float lo, hi;
            unpack2(acc[i][j], lo, hi);
            float2 o;
            o.x = lo + bias[n];
            o.y = hi + bias[n + 1];
            if (RELU) { o.x = fmaxf(o.x, 0.f); o.y = fmaxf(o.y, 0.f); }
            if (ADDY) {
                const float2 yv = *(const float2*)&Y[(size_t)m * Nout + n];
                o.x += bscale * yv.x;
                o.y += bscale * yv.y;
            }
            *(float2*)&C[(size_t)m * Nout + n] = o;
        }
    }
}

// ---------------- launch ----------------
extern "C" void kernel_launch(void* const* d_in, const int* in_sizes, int n_in,
                              void* d_out, int out_size) {
    const float* x    = (const float*)d_in[0];
    const float* y    = (const float*)d_in[1];
    const float* W1   = (const float*)d_in[2];
    const float* b1   = (const float*)d_in[3];
    const float* W2   = (const float*)d_in[4];
    const float* b2   = (const float*)d_in[5];
    const float* bn1g = (const float*)d_in[6];
    const float* bn1b = (const float*)d_in[7];
    const float* bn2g = (const float*)d_in[8];
    const float* bn2b = (const float*)d_in[9];
    const float* beta = (const float*)d_in[10];
    float* out = (float*)d_out;

    float *h1, *W1f, *W2f, *b1f, *b2f, *sc1, *sh1, *sc2, *sh2;
    cudaGetSymbolAddress((void**)&h1,  g_h1);
    cudaGetSymbolAddress((void**)&W1f, g_W1f);
    cudaGetSymbolAddress((void**)&W2f, g_W2f);
    cudaGetSymbolAddress((void**)&b1f, g_b1f);
    cudaGetSymbolAddress((void**)&b2f, g_b2f);
    cudaGetSymbolAddress((void**)&sc1, g_scale1);
    cudaGetSymbolAddress((void**)&sh1, g_shift1);
    cudaGetSymbolAddress((void**)&sc2, g_scale2);
    cudaGetSymbolAddress((void**)&sh2, g_shift2);

    // ---- layer 1: BN1 stats -> fold -> GEMM1 (+bias, +relu) ----
    col_stats_partial<<<dim3(NFEAT / 256, RS), 256>>>(x, NFEAT, NROWS / RS);
    col_stats_finalize<<<NFEAT / 256, 256>>>(bn1g, bn1b, sc1, sh1, NFEAT);
    fold_weights<<<NHID, 256>>>(W1, b1, sc1, sh1, W1f, b1f, NFEAT);
    gemm_bias<true, false><<<dim3(NHID / BN, NROWS / BM), 256>>>(
        x, W1f, b1f, nullptr, nullptr, h1, NROWS, NHID, NFEAT);

    // ---- layer 2: BN2 stats -> fold -> GEMM2 (+bias, +beta*y) ----
    col_stats_partial<<<dim3(NHID / 256, RS), 256>>>(h1, NHID, NROWS / RS);
    col_stats_finalize<<<NHID / 256, 256>>>(bn2g, bn2b, sc2, sh2, NHID);
    fold_weights<<<NCLS, 256>>>(W2, b2, sc2, sh2, W2f, b2f, NHID);
    gemm_bias<false, true><<<dim3(NCLS / BN, NROWS / BM), 256>>>(
        h1, W2f, b2f, y, beta, out, NROWS, NCLS, NHID);
}

// round 3
// speedup vs baseline: 2.8176x; 2.8176x over previous
#include <cuda_runtime.h>
#include <cuda_bf16.h>
#include <cstdint>

#define NROWS 32768
#define NFEAT 2048
#define NHID  4096
#define NCLS  512
#define RS    32

// GEMM tiling: 128x128 CTA tile, BK=32, 8 warps (2x4), warp tile 64x32
#define BM 128
#define BN 128
#define BKC 32
#define STAGE 32768          // Ahi 8K + Alo 8K + Bhi 8K + Blo 8K
#define NSTAGE 4
#define SMEM_DYN (NSTAGE * STAGE)

// ---------------- device scratch ----------------
__device__ __nv_bfloat16 g_xhi [(size_t)NROWS * NFEAT];
__device__ __nv_bfloat16 g_xlo [(size_t)NROWS * NFEAT];
__device__ __nv_bfloat16 g_h1hi[(size_t)NROWS * NHID];
__device__ __nv_bfloat16 g_h1lo[(size_t)NROWS * NHID];
__device__ __nv_bfloat16 g_w1hi[(size_t)NHID  * NFEAT];
__device__ __nv_bfloat16 g_w1lo[(size_t)NHID  * NFEAT];
__device__ __nv_bfloat16 g_w2hi[(size_t)NCLS  * NHID];
__device__ __nv_bfloat16 g_w2lo[(size_t)NCLS  * NHID];
__device__ float  g_b1f[NHID];
__device__ float  g_b2f[NCLS];
__device__ float  g_scale1[NFEAT], g_shift1[NFEAT];
__device__ float  g_scale2[NHID],  g_shift2[NHID];
__device__ double g_psum  [RS * NHID];
__device__ double g_psumsq[RS * NHID];

// ---------------- PTX helpers (family-portable only: sm_80-era) ----------------
__device__ __forceinline__ uint32_t smem_u32(const void* p) {
    uint32_t a;
    asm("{ .reg .u64 t; cvta.to.shared.u64 t, %1; cvt.u32.u64 %0, t; }" : "=r"(a) : "l"(p));
    return a;
}
__device__ __forceinline__ void cp16(uint32_t s, const void* g) {
    asm volatile("cp.async.cg.shared.global [%0], [%1], 16;" :: "r"(s), "l"(g));
}
__device__ __forceinline__ void cp_commit() { asm volatile("cp.async.commit_group;" ::: "memory"); }
__device__ __forceinline__ void cp_wait2()  { asm volatile("cp.async.wait_group 2;" ::: "memory"); }
__device__ __forceinline__ void cp_wait0()  { asm volatile("cp.async.wait_group 0;" ::: "memory"); }

__device__ __forceinline__ void ldsm_x4(uint32_t& d0, uint32_t& d1, uint32_t& d2, uint32_t& d3, uint32_t addr) {
    asm volatile("ldmatrix.sync.aligned.m8n8.x4.shared.b16 {%0,%1,%2,%3}, [%4];"
                 : "=r"(d0), "=r"(d1), "=r"(d2), "=r"(d3) : "r"(addr));
}
__device__ __forceinline__ void mma16816(float* c, const uint32_t* a, uint32_t b0, uint32_t b1) {
    asm volatile("mma.sync.aligned.m16n8k16.row.col.f32.bf16.bf16.f32 "
                 "{%0,%1,%2,%3}, {%4,%5,%6,%7}, {%8,%9}, {%0,%1,%2,%3};"
                 : "+f"(c[0]), "+f"(c[1]), "+f"(c[2]), "+f"(c[3])
                 : "r"(a[0]), "r"(a[1]), "r"(a[2]), "r"(a[3]), "r"(b0), "r"(b1));
}

// swizzled byte address inside a 128-row x 64B tile (16B chunk granularity).
// Conflict-free for both cp.async stores and ldmatrix reads (verified: 8 distinct
// 4-bank groups per 8 rows).
__device__ __forceinline__ uint32_t tswz(uint32_t base, int r, int c) {
    return base + r * 64 + ((c ^ ((r >> 1) & 3)) << 4);
}

// ---------------- stats / conversion kernels ----------------
__global__ void conv_stats_x(const float* __restrict__ X,
                             __nv_bfloat16* __restrict__ Xhi, __nv_bfloat16* __restrict__ Xlo,
                             int C, int rowsPer) {
    int c = blockIdx.x * 256 + threadIdx.x;
    size_t base = (size_t)blockIdx.y * rowsPer * C + c;
    double s = 0, q = 0;
    for (int r = 0; r < rowsPer; r++) {
        float v = X[base + (size_t)r * C];
        __nv_bfloat16 h = __float2bfloat16(v);
        Xhi[base + (size_t)r * C] = h;
        Xlo[base + (size_t)r * C] = __float2bfloat16(v - __bfloat162float(h));
        s += v; q += (double)v * v;
    }
    g_psum  [blockIdx.y * C + c] = s;
    g_psumsq[blockIdx.y * C + c] = q;
}

__global__ void stats_split(const __nv_bfloat16* __restrict__ Hi,
                            const __nv_bfloat16* __restrict__ Lo, int C, int rowsPer) {
    int c = blockIdx.x * 256 + threadIdx.x;
    size_t base = (size_t)blockIdx.y * rowsPer * C + c;
    double s = 0, q = 0;
    for (int r = 0; r < rowsPer; r++) {
        float v = __bfloat162float(Hi[base + (size_t)r * C]) + __bfloat162float(Lo[base + (size_t)r * C]);
        s += v; q += (double)v * v;
    }
    g_psum  [blockIdx.y * C + c] = s;
    g_psumsq[blockIdx.y * C + c] = q;
}

__global__ void col_stats_finalize(const float* __restrict__ gamma, const float* __restrict__ bnb,
                                   float* __restrict__ scale, float* __restrict__ shift, int C) {
    int c = blockIdx.x * 256 + threadIdx.x;
    double s = 0, q = 0;
    for (int i = 0; i < RS; i++) { s += g_psum[i * C + c]; q += g_psumsq[i * C + c]; }
    double mu  = s * (1.0 / NROWS);
    double var = q * (1.0 / NROWS) - mu * mu;
    float a = rsqrtf((float)var + 1e-5f) * gamma[c];
    scale[c] = a;
    shift[c] = bnb[c] - (float)mu * a;
}

__global__ void fold_split(const float* __restrict__ W, const float* __restrict__ bias,
                           const float* __restrict__ scale, const float* __restrict__ shift,
                           __nv_bfloat16* __restrict__ Whi, __nv_bfloat16* __restrict__ Wlo,
                           float* __restrict__ bf, int K) {
    int j = blockIdx.x;
    const float* Wr = W + (size_t)j * K;
    float dot = 0.f;
    for (int k = threadIdx.x; k < K; k += 256) {
        float w = Wr[k];
        float wf = w * scale[k];
        __nv_bfloat16 h = __float2bfloat16(wf);
        Whi[(size_t)j * K + k] = h;
        Wlo[(size_t)j * K + k] = __float2bfloat16(wf - __bfloat162float(h));
        dot += w * shift[k];
    }
    __shared__ float red[256];
    red[threadIdx.x] = dot;
    __syncthreads();
    for (int s = 128; s > 0; s >>= 1) {
        if (threadIdx.x < s) red[threadIdx.x] += red[threadIdx.x + s];
        __syncthreads();
    }
    if (threadIdx.x == 0) bf[j] = bias[j] + red[0];
}

// ---------------- mma.sync GEMM: C = (Ahi+Alo)[M,K] @ (Bhi+Blo)[N,K]^T ----------------
template <bool L2E>
__global__ __launch_bounds__(256, 1)
void gemm_mma(const __nv_bfloat16* __restrict__ Ahi, const __nv_bfloat16* __restrict__ Alo,
              const __nv_bfloat16* __restrict__ Bhi, const __nv_bfloat16* __restrict__ Blo,
              const float* __restrict__ bias, const float* __restrict__ Y,
              const float* __restrict__ betap, float* __restrict__ Cout,
              __nv_bfloat16* __restrict__ Chi, __nv_bfloat16* __restrict__ Clo,
              int K, int Nout) {
    extern __shared__ __align__(1024) char smem[];
    const uint32_t sb = smem_u32(smem);
    const int tid  = threadIdx.x;
    const int wid  = tid >> 5;
    const int lane = tid & 31;
    const int wm   = (wid >> 2) * 64;      // warp m offset in tile
    const int wn   = (wid & 3) * 32;       // warp n offset in tile

    const int ldb = K * 2;  // row stride, bytes
    const char* gAhi = (const char*)(Ahi + (size_t)(blockIdx.y * BM) * K);
    const char* gAlo = (const char*)(Alo + (size_t)(blockIdx.y * BM) * K);
    const char* gBhi = (const char*)(Bhi + (size_t)(blockIdx.x * BN) * K);
    const char* gBlo = (const char*)(Blo + (size_t)(blockIdx.x * BN) * K);
    const int NC = K / BKC;

    auto load_stage = [&](int ch, int st) {
        uint32_t s0 = sb + st * STAGE;
        size_t kb = (size_t)ch * 64;
#pragma unroll
        for (int t = 0; t < 2; t++) {
            int o = tid + t * 256;
            int r = o >> 2, c = o & 3;
            uint32_t so = (uint32_t)r * 64 + ((uint32_t)(c ^ ((r >> 1) & 3)) << 4);
            size_t go = (size_t)r * ldb + kb + c * 16;
            cp16(s0 + so,         gAhi + go);
            cp16(s0 + 8192 + so,  gAlo + go);
            cp16(s0 + 16384 + so, gBhi + go);
            cp16(s0 + 24576 + so, gBlo + go);
        }
    };

    float acc[4][4][4];
#pragma unroll
    for (int i = 0; i < 4; i++)
#pragma unroll
        for (int j = 0; j < 4; j++)
#pragma unroll
            for (int r = 0; r < 4; r++) acc[i][j][r] = 0.f;

    // prologue
#pragma unroll
    for (int s = 0; s < NSTAGE - 1; s++) { load_stage(s, s); cp_commit(); }

    for (int i = 0; i < NC; i++) {
        cp_wait2();
        __syncthreads();
        const uint32_t st = sb + (i % NSTAGE) * STAGE;
        const uint32_t sAhi = st, sAlo = st + 8192, sBhi = st + 16384, sBlo = st + 24576;

#pragma unroll
        for (int s = 0; s < 2; s++) {
            // ---- load fragments ----
            uint32_t ah[4][4], al[4][4], bh[2][4], bl[2][4];
            const int ar = wm + (lane & 15);
            const int ac = s * 2 + (lane >> 4);
#pragma unroll
            for (int mi = 0; mi < 4; mi++) {
                uint32_t adr = tswz(sAhi, ar + mi * 16, ac);
                ldsm_x4(ah[mi][0], ah[mi][1], ah[mi][2], ah[mi][3], adr);
                adr = tswz(sAlo, ar + mi * 16, ac);
                ldsm_x4(al[mi][0], al[mi][1], al[mi][2], al[mi][3], adr);
            }
            const int br = wn + (lane & 7) + ((lane & 16) ? 8 : 0);
            const int bc = s * 2 + ((lane >> 3) & 1);
#pragma unroll
            for (int nj = 0; nj < 2; nj++) {
                uint32_t adr = tswz(sBhi, br + nj * 16, bc);
                ldsm_x4(bh[nj][0], bh[nj][1], bh[nj][2], bh[nj][3], adr);
                adr = tswz(sBlo, br + nj * 16, bc);
                ldsm_x4(bl[nj][0], bl[nj][1], bl[nj][2], bl[nj][3], adr);
            }
            // ---- mma: 3 passes ----
#pragma unroll
            for (int mi = 0; mi < 4; mi++)
#pragma unroll
                for (int jj = 0; jj < 4; jj++) {
                    uint32_t b0h = bh[jj >> 1][(jj & 1) * 2], b1h = bh[jj >> 1][(jj & 1) * 2 + 1];
                    uint32_t b0l = bl[jj >> 1][(jj & 1) * 2], b1l = bl[jj >> 1][(jj & 1) * 2 + 1];
                    mma16816(acc[mi][jj], ah[mi], b0h, b1h);
                    mma16816(acc[mi][jj], al[mi], b0h, b1h);
                    mma16816(acc[mi][jj], ah[mi], b0l, b1l);
                }
        }
        if (i + NSTAGE - 1 < NC) load_stage(i + NSTAGE - 1, (i + NSTAGE - 1) % NSTAGE);
        cp_commit();
    }
    cp_wait0();

    // ---- epilogue ----
    const int bm_ = blockIdx.y * BM, bn_ = blockIdx.x * BN;
    const float bsc = L2E ? __ldg(betap) : 0.f;
#pragma unroll
    for (int mi = 0; mi < 4; mi++) {
#pragma unroll
        for (int jj = 0; jj < 4; jj++) {
            const int row0 = bm_ + wm + mi * 16 + (lane >> 2);
            const int col  = bn_ + wn + jj * 8 + 2 * (lane & 3);
            const float bb0 = __ldg(&bias[col]), bb1 = __ldg(&bias[col + 1]);
#pragma unroll
            for (int h = 0; h < 2; h++) {       // h=0: row0, h=1: row0+8
                const int row = row0 + h * 8;
                float v0 = acc[mi][jj][h * 2 + 0] + bb0;
                float v1 = acc[mi][jj][h * 2 + 1] + bb1;
                if (!L2E) {
                    v0 = fmaxf(v0, 0.f); v1 = fmaxf(v1, 0.f);
                    __nv_bfloat16 h0 = __float2bfloat16(v0);
                    __nv_bfloat16 h1 = __float2bfloat16(v1);
                    __nv_bfloat162 hv; hv.x = h0; hv.y = h1;
                    __nv_bfloat162 lv;
                    lv.x = __float2bfloat16(v0 - __bfloat162float(h0));
                    lv.y = __float2bfloat16(v1 - __bfloat162float(h1));
                    *(__nv_bfloat162*)(Chi + (size_t)row * Nout + col) = hv;
                    *(__nv_bfloat162*)(Clo + (size_t)row * Nout + col) = lv;
                } else {
                    const float2 yv = *(const float2*)(Y + (size_t)row * Nout + col);
                    float2 o;
                    o.x = v0 + bsc * yv.x;
                    o.y = v1 + bsc * yv.y;
                    *(float2*)(Cout + (size_t)row * Nout + col) = o;
                }
            }
        }
    }
}

// ---------------- launch ----------------
extern "C" void kernel_launch(void* const* d_in, const int* in_sizes, int n_in,
                              void* d_out, int out_size) {
    const float* x    = (const float*)d_in[0];
    const float* y    = (const float*)d_in[1];
    const float* W1   = (const float*)d_in[2];
    const float* b1   = (const float*)d_in[3];
    const float* W2   = (const float*)d_in[4];
    const float* b2   = (const float*)d_in[5];
    const float* bn1g = (const float*)d_in[6];
    const float* bn1b = (const float*)d_in[7];
    const float* bn2g = (const float*)d_in[8];
    const float* bn2b = (const float*)d_in[9];
    const float* beta = (const float*)d_in[10];
    float* out = (float*)d_out;

    __nv_bfloat16 *xhi, *xlo, *h1hi, *h1lo, *w1hi, *w1lo, *w2hi, *w2lo;
    float *b1f, *b2f, *sc1, *sh1, *sc2, *sh2;
    cudaGetSymbolAddress((void**)&xhi,  g_xhi);
    cudaGetSymbolAddress((void**)&xlo,  g_xlo);
    cudaGetSymbolAddress((void**)&h1hi, g_h1hi);
    cudaGetSymbolAddress((void**)&h1lo, g_h1lo);
    cudaGetSymbolAddress((void**)&w1hi, g_w1hi);
    cudaGetSymbolAddress((void**)&w1lo, g_w1lo);
    cudaGetSymbolAddress((void**)&w2hi, g_w2hi);
    cudaGetSymbolAddress((void**)&w2lo, g_w2lo);
    cudaGetSymbolAddress((void**)&b1f,  g_b1f);
    cudaGetSymbolAddress((void**)&b2f,  g_b2f);
    cudaGetSymbolAddress((void**)&sc1,  g_scale1);
    cudaGetSymbolAddress((void**)&sh1,  g_shift1);
    cudaGetSymbolAddress((void**)&sc2,  g_scale2);
    cudaGetSymbolAddress((void**)&sh2,  g_shift2);

    cudaFuncSetAttribute(gemm_mma<false>, cudaFuncAttributeMaxDynamicSharedMemorySize, SMEM_DYN);
    cudaFuncSetAttribute(gemm_mma<true>,  cudaFuncAttributeMaxDynamicSharedMemorySize, SMEM_DYN);

    // layer 1
    conv_stats_x<<<dim3(NFEAT / 256, RS), 256>>>(x, xhi, xlo, NFEAT, NROWS / RS);
    col_stats_finalize<<<NFEAT / 256, 256>>>(bn1g, bn1b, sc1, sh1, NFEAT);
    fold_split<<<NHID, 256>>>(W1, b1, sc1, sh1, w1hi, w1lo, b1f, NFEAT);
    gemm_mma<false><<<dim3(NHID / BN, NROWS / BM), 256, SMEM_DYN>>>(
        xhi, xlo, w1hi, w1lo, b1f, nullptr, nullptr, nullptr, h1hi, h1lo, NFEAT, NHID);

    // layer 2
    stats_split<<<dim3(NHID / 256, RS), 256>>>(h1hi, h1lo, NHID, NROWS / RS);
    col_stats_finalize<<<NHID / 256, 256>>>(bn2g, bn2b, sc2, sh2, NHID);
    fold_split<<<NCLS, 256>>>(W2, b2, sc2, sh2, w2hi, w2lo, b2f, NHID);
    gemm_mma<true><<<dim3(NCLS / BN, NROWS / BM), 256, SMEM_DYN>>>(
        h1hi, h1lo, w2hi, w2lo, b2f, y, beta, out, nullptr, nullptr, NHID, NCLS);
}

// round 4
// speedup vs baseline: 3.0773x; 1.0922x over previous
#include <cuda_runtime.h>
#include <cuda_bf16.h>
#include <cstdint>

#define NROWS 32768
#define NFEAT 2048
#define NHID  4096
#define NCLS  512
#define RS    32

// GEMM tiling: 128x128 CTA tile, BK=32, 8 warps (2x4), warp tile 64x32
#define BM 128
#define BN 128
#define BKC 32
#define STAGE 32768          // Ahi 8K + Alo 8K + Bhi 8K + Blo 8K
#define NSTAGE 3
#define SMEM_DYN (NSTAGE * STAGE)

// ---------------- device scratch ----------------
__device__ __nv_bfloat16 g_xhi [(size_t)NROWS * NFEAT];
__device__ __nv_bfloat16 g_xlo [(size_t)NROWS * NFEAT];
__device__ __nv_bfloat16 g_h1hi[(size_t)NROWS * NHID];
__device__ __nv_bfloat16 g_h1lo[(size_t)NROWS * NHID];
__device__ __nv_bfloat16 g_w1hi[(size_t)NHID  * NFEAT];
__device__ __nv_bfloat16 g_w1lo[(size_t)NHID  * NFEAT];
__device__ __nv_bfloat16 g_w2hi[(size_t)NCLS  * NHID];
__device__ __nv_bfloat16 g_w2lo[(size_t)NCLS  * NHID];
__device__ float  g_b1f[NHID];
__device__ float  g_b2f[NCLS];
__device__ float  g_scale1[NFEAT], g_shift1[NFEAT];
__device__ float  g_scale2[NHID],  g_shift2[NHID];
__device__ float  g_psum  [RS * NHID];
__device__ float  g_psumsq[RS * NHID];

// ---------------- PTX helpers (family-portable only: sm_80-era) ----------------
__device__ __forceinline__ uint32_t smem_u32(const void* p) {
    uint32_t a;
    asm("{ .reg .u64 t; cvta.to.shared.u64 t, %1; cvt.u32.u64 %0, t; }" : "=r"(a) : "l"(p));
    return a;
}
__device__ __forceinline__ void cp16(uint32_t s, const void* g) {
    asm volatile("cp.async.cg.shared.global [%0], [%1], 16;" :: "r"(s), "l"(g));
}
__device__ __forceinline__ void cp_commit() { asm volatile("cp.async.commit_group;" ::: "memory"); }
__device__ __forceinline__ void cp_wait1()  { asm volatile("cp.async.wait_group 1;" ::: "memory"); }
__device__ __forceinline__ void cp_wait0()  { asm volatile("cp.async.wait_group 0;" ::: "memory"); }

__device__ __forceinline__ void ldsm_x4(uint32_t& d0, uint32_t& d1, uint32_t& d2, uint32_t& d3, uint32_t addr) {
    asm volatile("ldmatrix.sync.aligned.m8n8.x4.shared.b16 {%0,%1,%2,%3}, [%4];"
                 : "=r"(d0), "=r"(d1), "=r"(d2), "=r"(d3) : "r"(addr));
}
__device__ __forceinline__ void mma16816(float* c, const uint32_t* a, uint32_t b0, uint32_t b1) {
    asm volatile("mma.sync.aligned.m16n8k16.row.col.f32.bf16.bf16.f32 "
                 "{%0,%1,%2,%3}, {%4,%5,%6,%7}, {%8,%9}, {%0,%1,%2,%3};"
                 : "+f"(c[0]), "+f"(c[1]), "+f"(c[2]), "+f"(c[3])
                 : "r"(a[0]), "r"(a[1]), "r"(a[2]), "r"(a[3]), "r"(b0), "r"(b1));
}

// swizzled byte address inside a 128-row x 64B tile (16B chunk granularity).
__device__ __forceinline__ uint32_t tswz(uint32_t base, int r, int c) {
    return base + r * 64 + ((c ^ ((r >> 1) & 3)) << 4);
}

// ---------------- stats / conversion kernels (fp32 partials, vectorized) ----------------
// Each thread owns 4 consecutive columns; grid (C/1024, RS); 1024-row chunks.
__global__ __launch_bounds__(256)
void conv_stats_x(const float* __restrict__ X,
                  __nv_bfloat16* __restrict__ Xhi, __nv_bfloat16* __restrict__ Xlo,
                  int C, int rowsPer) {
    const int c4 = (blockIdx.x * 256 + threadIdx.x) * 4;
    const size_t base = (size_t)blockIdx.y * rowsPer * C + c4;
    float s0 = 0, s1 = 0, s2 = 0, s3 = 0;
    float q0 = 0, q1 = 0, q2 = 0, q3 = 0;
    for (int r = 0; r < rowsPer; r += 2) {
#pragma unroll
        for (int u = 0; u < 2; u++) {
            const size_t o = base + (size_t)(r + u) * C;
            float4 v = *(const float4*)(X + o);
            s0 += v.x; q0 = fmaf(v.x, v.x, q0);
            s1 += v.y; q1 = fmaf(v.y, v.y, q1);
            s2 += v.z; q2 = fmaf(v.z, v.z, q2);
            s3 += v.w; q3 = fmaf(v.w, v.w, q3);
            __nv_bfloat16 h0 = __float2bfloat16(v.x), h1 = __float2bfloat16(v.y);
            __nv_bfloat16 h2 = __float2bfloat16(v.z), h3 = __float2bfloat16(v.w);
            __nv_bfloat162 hA; hA.x = h0; hA.y = h1;
            __nv_bfloat162 hB; hB.x = h2; hB.y = h3;
            *(uint2*)(Xhi + o) = make_uint2(*(uint32_t*)&hA, *(uint32_t*)&hB);
            __nv_bfloat162 lA, lB;
            lA.x = __float2bfloat16(v.x - __bfloat162float(h0));
            lA.y = __float2bfloat16(v.y - __bfloat162float(h1));
            lB.x = __float2bfloat16(v.z - __bfloat162float(h2));
            lB.y = __float2bfloat16(v.w - __bfloat162float(h3));
            *(uint2*)(Xlo + o) = make_uint2(*(uint32_t*)&lA, *(uint32_t*)&lB);
        }
    }
    const int pb = blockIdx.y * C + c4;
    g_psum[pb + 0] = s0; g_psum[pb + 1] = s1; g_psum[pb + 2] = s2; g_psum[pb + 3] = s3;
    g_psumsq[pb + 0] = q0; g_psumsq[pb + 1] = q1; g_psumsq[pb + 2] = q2; g_psumsq[pb + 3] = q3;
}

// Each thread owns 8 consecutive bf16 columns (16B hi + 16B lo per row).
__global__ __launch_bounds__(256)
void stats_split(const __nv_bfloat16* __restrict__ Hi,
                 const __nv_bfloat16* __restrict__ Lo, int C, int rowsPer) {
    const int c8 = (blockIdx.x * 256 + threadIdx.x) * 8;
    const size_t base = (size_t)blockIdx.y * rowsPer * C + c8;
    float s[8], q[8];
#pragma unroll
    for (int j = 0; j < 8; j++) { s[j] = 0.f; q[j] = 0.f; }
    for (int r = 0; r < rowsPer; r += 2) {
#pragma unroll
        for (int u = 0; u < 2; u++) {
            const size_t o = base + (size_t)(r + u) * C;
            uint4 hv = *(const uint4*)(Hi + o);
            uint4 lv = *(const uint4*)(Lo + o);
            const uint32_t* hp = &hv.x;
            const uint32_t* lp = &lv.x;
#pragma unroll
            for (int t = 0; t < 4; t++) {
                float2 hf = __bfloat1622float2(*(const __nv_bfloat162*)&hp[t]);
                float2 lf = __bfloat1622float2(*(const __nv_bfloat162*)&lp[t]);
                float v0 = hf.x + lf.x, v1 = hf.y + lf.y;
                s[t * 2 + 0] += v0; q[t * 2 + 0] = fmaf(v0, v0, q[t * 2 + 0]);
                s[t * 2 + 1] += v1; q[t * 2 + 1] = fmaf(v1, v1, q[t * 2 + 1]);
            }
        }
    }
    const int pb = blockIdx.y * C + c8;
#pragma unroll
    for (int j = 0; j < 8; j++) { g_psum[pb + j] = s[j]; g_psumsq[pb + j] = q[j]; }
}

__global__ void col_stats_finalize(const float* __restrict__ gamma, const float* __restrict__ bnb,
                                   float* __restrict__ scale, float* __restrict__ shift, int C) {
    int c = blockIdx.x * 256 + threadIdx.x;
    double s = 0, q = 0;
    for (int i = 0; i < RS; i++) { s += (double)g_psum[i * C + c]; q += (double)g_psumsq[i * C + c]; }
    double mu  = s * (1.0 / NROWS);
    double var = q * (1.0 / NROWS) - mu * mu;
    float a = rsqrtf((float)var + 1e-5f) * gamma[c];
    scale[c] = a;
    shift[c] = bnb[c] - (float)mu * a;
}

__global__ void fold_split(const float* __restrict__ W, const float* __restrict__ bias,
                           const float* __restrict__ scale, const float* __restrict__ shift,
                           __nv_bfloat16* __restrict__ Whi, __nv_bfloat16* __restrict__ Wlo,
                           float* __restrict__ bf, int K) {
    int j = blockIdx.x;
    const float* Wr = W + (size_t)j * K;
    float dot = 0.f;
    for (int k = threadIdx.x; k < K; k += 256) {
        float w = Wr[k];
        float wf = w * scale[k];
        __nv_bfloat16 h = __float2bfloat16(wf);
        Whi[(size_t)j * K + k] = h;
        Wlo[(size_t)j * K + k] = __float2bfloat16(wf - __bfloat162float(h));
        dot += w * shift[k];
    }
    __shared__ float red[256];
    red[threadIdx.x] = dot;
    __syncthreads();
    for (int s = 128; s > 0; s >>= 1) {
        if (threadIdx.x < s) red[threadIdx.x] += red[threadIdx.x + s];
        __syncthreads();
    }
    if (threadIdx.x == 0) bf[j] = bias[j] + red[0];
}

// ---------------- mma.sync GEMM: C = (Ahi+Alo)[M,K] @ (Bhi+Blo)[N,K]^T ----------------
template <bool L2E>
__global__ __launch_bounds__(256, 2)
void gemm_mma(const __nv_bfloat16* __restrict__ Ahi, const __nv_bfloat16* __restrict__ Alo,
              const __nv_bfloat16* __restrict__ Bhi, const __nv_bfloat16* __restrict__ Blo,
              const float* __restrict__ bias, const float* __restrict__ Y,
              const float* __restrict__ betap, float* __restrict__ Cout,
              __nv_bfloat16* __restrict__ Chi, __nv_bfloat16* __restrict__ Clo,
              int K, int Nout) {
    extern __shared__ __align__(1024) char smem[];
    const uint32_t sb = smem_u32(smem);
    const int tid  = threadIdx.x;
    const int wid  = tid >> 5;
    const int lane = tid & 31;
    const int wm   = (wid >> 2) * 64;      // warp m offset in tile
    const int wn   = (wid & 3) * 32;       // warp n offset in tile

    const int ldb = K * 2;  // row stride, bytes
    const char* gAhi = (const char*)(Ahi + (size_t)(blockIdx.y * BM) * K);
    const char* gAlo = (const char*)(Alo + (size_t)(blockIdx.y * BM) * K);
    const char* gBhi = (const char*)(Bhi + (size_t)(blockIdx.x * BN) * K);
    const char* gBlo = (const char*)(Blo + (size_t)(blockIdx.x * BN) * K);
    const int NC = K / BKC;

    auto load_stage = [&](int ch, int st) {
        uint32_t s0 = sb + st * STAGE;
        size_t kb = (size_t)ch * 64;
#pragma unroll
        for (int t = 0; t < 2; t++) {
            int o = tid + t * 256;
            int r = o >> 2, c = o & 3;
            uint32_t so = (uint32_t)r * 64 + ((uint32_t)(c ^ ((r >> 1) & 3)) << 4);
            size_t go = (size_t)r * ldb + kb + c * 16;
            cp16(s0 + so,         gAhi + go);
            cp16(s0 + 8192 + so,  gAlo + go);
            cp16(s0 + 16384 + so, gBhi + go);
            cp16(s0 + 24576 + so, gBlo + go);
        }
    };

    float acc[4][4][4];
#pragma unroll
    for (int i = 0; i < 4; i++)
#pragma unroll
        for (int j = 0; j < 4; j++)
#pragma unroll
            for (int r = 0; r < 4; r++) acc[i][j][r] = 0.f;

    // prologue: fill NSTAGE-1 stages
#pragma unroll
    for (int s = 0; s < NSTAGE - 1; s++) { load_stage(s, s); cp_commit(); }

    for (int i = 0; i < NC; i++) {
        cp_wait1();
        __syncthreads();
        // issue next-stage loads FIRST so they overlap this chunk's compute
        if (i + NSTAGE - 1 < NC) { load_stage(i + NSTAGE - 1, (i + NSTAGE - 1) % NSTAGE); }
        cp_commit();

        const uint32_t st = sb + (i % NSTAGE) * STAGE;
        const uint32_t sAhi = st, sAlo = st + 8192, sBhi = st + 16384, sBlo = st + 24576;

#pragma unroll
        for (int s = 0; s < 2; s++) {
            uint32_t af[4][4], bfr[2][4], tf[4][4];
            const int ar = wm + (lane & 15);
            const int ac = s * 2 + (lane >> 4);
            const int br = wn + (lane & 7) + ((lane & 16) ? 8 : 0);
            const int bc = s * 2 + ((lane >> 3) & 1);
            // hi A, hi B
#pragma unroll
            for (int mi = 0; mi < 4; mi++)
                ldsm_x4(af[mi][0], af[mi][1], af[mi][2], af[mi][3], tswz(sAhi, ar + mi * 16, ac));
#pragma unroll
            for (int nj = 0; nj < 2; nj++)
                ldsm_x4(bfr[nj][0], bfr[nj][1], bfr[nj][2], bfr[nj][3], tswz(sBhi, br + nj * 16, bc));
#pragma unroll
            for (int mi = 0; mi < 4; mi++)
#pragma unroll
                for (int jj = 0; jj < 4; jj++)
                    mma16816(acc[mi][jj], af[mi], bfr[jj >> 1][(jj & 1) * 2], bfr[jj >> 1][(jj & 1) * 2 + 1]);
            // lo A x hi B
#pragma unroll
            for (int mi = 0; mi < 4; mi++)
                ldsm_x4(tf[mi][0], tf[mi][1], tf[mi][2], tf[mi][3], tswz(sAlo, ar + mi * 16, ac));
#pragma unroll
            for (int mi = 0; mi < 4; mi++)
#pragma unroll
                for (int jj = 0; jj < 4; jj++)
                    mma16816(acc[mi][jj], tf[mi], bfr[jj >> 1][(jj & 1) * 2], bfr[jj >> 1][(jj & 1) * 2 + 1]);
            // hi A x lo B (overwrite B regs)
#pragma unroll
            for (int nj = 0; nj < 2; nj++)
                ldsm_x4(bfr[nj][0], bfr[nj][1], bfr[nj][2], bfr[nj][3], tswz(sBlo, br + nj * 16, bc));
#pragma unroll
            for (int mi = 0; mi < 4; mi++)
#pragma unroll
                for (int jj = 0; jj < 4; jj++)
                    mma16816(acc[mi][jj], af[mi], bfr[jj >> 1][(jj & 1) * 2], bfr[jj >> 1][(jj & 1) * 2 + 1]);
        }
    }
    cp_wait0();

    // ---- epilogue ----
    const int bm_ = blockIdx.y * BM, bn_ = blockIdx.x * BN;
    const float bsc = L2E ? __ldg(betap) : 0.f;
#pragma unroll
    for (int mi = 0; mi < 4; mi++) {
#pragma unroll
        for (int jj = 0; jj < 4; jj++) {
            const int row0 = bm_ + wm + mi * 16 + (lane >> 2);
            const int col  = bn_ + wn + jj * 8 + 2 * (lane & 3);
            const float bb0 = __ldg(&bias[col]), bb1 = __ldg(&bias[col + 1]);
#pragma unroll
            for (int h = 0; h < 2; h++) {
                const int row = row0 + h * 8;
                float v0 = acc[mi][jj][h * 2 + 0] + bb0;
                float v1 = acc[mi][jj][h * 2 + 1] + bb1;
                if (!L2E) {
                    v0 = fmaxf(v0, 0.f); v1 = fmaxf(v1, 0.f);
                    __nv_bfloat16 h0 = __float2bfloat16(v0);
                    __nv_bfloat16 h1 = __float2bfloat16(v1);
                    __nv_bfloat162 hv; hv.x = h0; hv.y = h1;
                    __nv_bfloat162 lv;
                    lv.x = __float2bfloat16(v0 - __bfloat162float(h0));
                    lv.y = __float2bfloat16(v1 - __bfloat162float(h1));
                    *(__nv_bfloat162*)(Chi + (size_t)row * Nout + col) = hv;
                    *(__nv_bfloat162*)(Clo + (size_t)row * Nout + col) = lv;
                } else {
                    const float2 yv = *(const float2*)(Y + (size_t)row * Nout + col);
                    float2 o;
                    o.x = v0 + bsc * yv.x;
                    o.y = v1 + bsc * yv.y;
                    *(float2*)(Cout + (size_t)row * Nout + col) = o;
                }
            }
        }
    }
}

// ---------------- launch ----------------
extern "C" void kernel_launch(void* const* d_in, const int* in_sizes, int n_in,
                              void* d_out, int out_size) {
    const float* x    = (const float*)d_in[0];
    const float* y    = (const float*)d_in[1];
    const float* W1   = (const float*)d_in[2];
    const float* b1   = (const float*)d_in[3];
    const float* W2   = (const float*)d_in[4];
    const float* b2   = (const float*)d_in[5];
    const float* bn1g = (const float*)d_in[6];
    const float* bn1b = (const float*)d_in[7];
    const float* bn2g = (const float*)d_in[8];
    const float* bn2b = (const float*)d_in[9];
    const float* beta = (const float*)d_in[10];
    float* out = (float*)d_out;

    __nv_bfloat16 *xhi, *xlo, *h1hi, *h1lo, *w1hi, *w1lo, *w2hi, *w2lo;
    float *b1f, *b2f, *sc1, *sh1, *sc2, *sh2;
    cudaGetSymbolAddress((void**)&xhi,  g_xhi);
    cudaGetSymbolAddress((void**)&xlo,  g_xlo);
    cudaGetSymbolAddress((void**)&h1hi, g_h1hi);
    cudaGetSymbolAddress((void**)&h1lo, g_h1lo);
    cudaGetSymbolAddress((void**)&w1hi, g_w1hi);
    cudaGetSymbolAddress((void**)&w1lo, g_w1lo);
    cudaGetSymbolAddress((void**)&w2hi, g_w2hi);
    cudaGetSymbolAddress((void**)&w2lo, g_w2lo);
    cudaGetSymbolAddress((void**)&b1f,  g_b1f);
    cudaGetSymbolAddress((void**)&b2f,  g_b2f);
    cudaGetSymbolAddress((void**)&sc1,  g_scale1);
    cudaGetSymbolAddress((void**)&sh1,  g_shift1);
    cudaGetSymbolAddress((void**)&sc2,  g_scale2);
    cudaGetSymbolAddress((void**)&sh2,  g_shift2);

    cudaFuncSetAttribute(gemm_mma<false>, cudaFuncAttributeMaxDynamicSharedMemorySize, SMEM_DYN);
    cudaFuncSetAttribute(gemm_mma<true>,  cudaFuncAttributeMaxDynamicSharedMemorySize, SMEM_DYN);

    // layer 1
    conv_stats_x<<<dim3(NFEAT / 1024, RS), 256>>>(x, xhi, xlo, NFEAT, NROWS / RS);
    col_stats_finalize<<<NFEAT / 256, 256>>>(bn1g, bn1b, sc1, sh1, NFEAT);
    fold_split<<<NHID, 256>>>(W1, b1, sc1, sh1, w1hi, w1lo, b1f, NFEAT);
    gemm_mma<false><<<dim3(NHID / BN, NROWS / BM), 256, SMEM_DYN>>>(
        xhi, xlo, w1hi, w1lo, b1f, nullptr, nullptr, nullptr, h1hi, h1lo, NFEAT, NHID);

    // layer 2
    stats_split<<<dim3(NHID / 2048, RS), 256>>>(h1hi, h1lo, NHID, NROWS / RS);
    col_stats_finalize<<<NHID / 256, 256>>>(bn2g, bn2b, sc2, sh2, NHID);
    fold_split<<<NCLS, 256>>>(W2, b2, sc2, sh2, w2hi, w2lo, b2f, NHID);
    gemm_mma<true><<<dim3(NCLS / BN, NROWS / BM), 256, SMEM_DYN>>>(
        h1hi, h1lo, w2hi, w2lo, b2f, y, beta, out, nullptr, nullptr, NHID, NCLS);
}

// round 6
// speedup vs baseline: 3.5334x; 1.1482x over previous
#include <cuda_runtime.h>
#include <cuda_bf16.h>
#include <cstdint>

#define NROWS 32768
#define NFEAT 2048
#define NHID  4096
#define NCLS  512
#define RSX   256            // partial-split factor for column stats

// GEMM tiling: 128x128 CTA tile, BK=32, 8 warps (2x4), warp tile 64x32
#define BM 128
#define BN 128
#define BKC 32
#define STAGE 32768          // Ahi 8K + Alo 8K + Bhi 8K + Blo 8K
#define NSTAGE 3
#define SMEM_DYN (NSTAGE * STAGE)

// ---------------- device scratch ----------------
__device__ __nv_bfloat16 g_xhi [(size_t)NROWS * NFEAT];
__device__ __nv_bfloat16 g_xlo [(size_t)NROWS * NFEAT];
__device__ __nv_bfloat16 g_h1hi[(size_t)NROWS * NHID];
__device__ __nv_bfloat16 g_h1lo[(size_t)NROWS * NHID];
__device__ __nv_bfloat16 g_w1hi[(size_t)NHID  * NFEAT];
__device__ __nv_bfloat16 g_w1lo[(size_t)NHID  * NFEAT];
__device__ __nv_bfloat16 g_w2hi[(size_t)NCLS  * NHID];
__device__ __nv_bfloat16 g_w2lo[(size_t)NCLS  * NHID];
__device__ float  g_b1f[NHID];
__device__ float  g_b2f[NCLS];
__device__ float  g_scale1[NFEAT], g_shift1[NFEAT];
__device__ float  g_scale2[NHID],  g_shift2[NHID];
__device__ float  g_psum  [(size_t)RSX * NHID];
__device__ float  g_psumsq[(size_t)RSX * NHID];

// ---------------- PTX helpers (family-portable only: sm_80-era) ----------------
__device__ __forceinline__ uint32_t smem_u32(const void* p) {
    uint32_t a;
    asm("{ .reg .u64 t; cvta.to.shared.u64 t, %1; cvt.u32.u64 %0, t; }" : "=r"(a) : "l"(p));
    return a;
}
__device__ __forceinline__ void cp16(uint32_t s, const void* g) {
    asm volatile("cp.async.cg.shared.global [%0], [%1], 16;" :: "r"(s), "l"(g));
}
__device__ __forceinline__ void cp_commit() { asm volatile("cp.async.commit_group;" ::: "memory"); }
__device__ __forceinline__ void cp_wait1()  { asm volatile("cp.async.wait_group 1;" ::: "memory"); }
__device__ __forceinline__ void cp_wait0()  { asm volatile("cp.async.wait_group 0;" ::: "memory"); }

__device__ __forceinline__ void ldsm_x4(uint32_t& d0, uint32_t& d1, uint32_t& d2, uint32_t& d3, uint32_t addr) {
    asm volatile("ldmatrix.sync.aligned.m8n8.x4.shared.b16 {%0,%1,%2,%3}, [%4];"
                 : "=r"(d0), "=r"(d1), "=r"(d2), "=r"(d3) : "r"(addr));
}
__device__ __forceinline__ void mma16816(float* c, const uint32_t* a, uint32_t b0, uint32_t b1) {
    asm volatile("mma.sync.aligned.m16n8k16.row.col.f32.bf16.bf16.f32 "
                 "{%0,%1,%2,%3}, {%4,%5,%6,%7}, {%8,%9}, {%0,%1,%2,%3};"
                 : "+f"(c[0]), "+f"(c[1]), "+f"(c[2]), "+f"(c[3])
                 : "r"(a[0]), "r"(a[1]), "r"(a[2]), "r"(a[3]), "r"(b0), "r"(b1));
}

// swizzled byte address inside a 128-row x 64B tile (16B chunk granularity).
__device__ __forceinline__ uint32_t tswz(uint32_t base, int r, int c) {
    return base + r * 64 + ((c ^ ((r >> 1) & 3)) << 4);
}

// ---------------- stats / conversion kernels (fp32 partials, wide grids) ----------------
// grid (C/1024, RSX); each thread owns 4 consecutive columns over 128 rows.
__global__ __launch_bounds__(256)
void conv_stats_x(const float* __restrict__ X,
                  __nv_bfloat16* __restrict__ Xhi, __nv_bfloat16* __restrict__ Xlo,
                  int C, int rowsPer) {
    const int c4 = (blockIdx.x * 256 + threadIdx.x) * 4;
    const size_t base = (size_t)blockIdx.y * rowsPer * C + c4;
    float s0 = 0, s1 = 0, s2 = 0, s3 = 0;
    float q0 = 0, q1 = 0, q2 = 0, q3 = 0;
    for (int r = 0; r < rowsPer; r += 4) {
#pragma unroll
        for (int u = 0; u < 4; u++) {
            const size_t o = base + (size_t)(r + u) * C;
            float4 v = *(const float4*)(X + o);
            s0 += v.x; q0 = fmaf(v.x, v.x, q0);
            s1 += v.y; q1 = fmaf(v.y, v.y, q1);
            s2 += v.z; q2 = fmaf(v.z, v.z, q2);
            s3 += v.w; q3 = fmaf(v.w, v.w, q3);
            __nv_bfloat16 h0 = __float2bfloat16(v.x), h1 = __float2bfloat16(v.y);
            __nv_bfloat16 h2 = __float2bfloat16(v.z), h3 = __float2bfloat16(v.w);
            __nv_bfloat162 hA; hA.x = h0; hA.y = h1;
            __nv_bfloat162 hB; hB.x = h2; hB.y = h3;
            *(uint2*)(Xhi + o) = make_uint2(*(uint32_t*)&hA, *(uint32_t*)&hB);
            __nv_bfloat162 lA, lB;
            lA.x = __float2bfloat16(v.x - __bfloat162float(h0));
            lA.y = __float2bfloat16(v.y - __bfloat162float(h1));
            lB.x = __float2bfloat16(v.z - __bfloat162float(h2));
            lB.y = __float2bfloat16(v.w - __bfloat162float(h3));
            *(uint2*)(Xlo + o) = make_uint2(*(uint32_t*)&lA, *(uint32_t*)&lB);
        }
    }
    const int pb = blockIdx.y * C + c4;
    g_psum[pb + 0] = s0; g_psum[pb + 1] = s1; g_psum[pb + 2] = s2; g_psum[pb + 3] = s3;
    g_psumsq[pb + 0] = q0; g_psumsq[pb + 1] = q1; g_psumsq[pb + 2] = q2; g_psumsq[pb + 3] = q3;
}

// grid (C/2048, RSX); each thread owns 8 consecutive bf16 columns over 128 rows.
__global__ __launch_bounds__(256)
void stats_split(const __nv_bfloat16* __restrict__ Hi,
                 const __nv_bfloat16* __restrict__ Lo, int C, int rowsPer) {
    const int c8 = (blockIdx.x * 256 + threadIdx.x) * 8;
    const size_t base = (size_t)blockIdx.y * rowsPer * C + c8;
    float s[8], q[8];
#pragma unroll
    for (int j = 0; j < 8; j++) { s[j] = 0.f; q[j] = 0.f; }
    for (int r = 0; r < rowsPer; r += 4) {
#pragma unroll
        for (int u = 0; u < 4; u++) {
            const size_t o = base + (size_t)(r + u) * C;
            uint4 hv = *(const uint4*)(Hi + o);
            uint4 lv = *(const uint4*)(Lo + o);
            const uint32_t* hp = &hv.x;
            const uint32_t* lp = &lv.x;
#pragma unroll
            for (int t = 0; t < 4; t++) {
                float2 hf = __bfloat1622float2(*(const __nv_bfloat162*)&hp[t]);
                float2 lf = __bfloat1622float2(*(const __nv_bfloat162*)&lp[t]);
                float v0 = hf.x + lf.x, v1 = hf.y + lf.y;
                s[t * 2 + 0] += v0; q[t * 2 + 0] = fmaf(v0, v0, q[t * 2 + 0]);
                s[t * 2 + 1] += v1; q[t * 2 + 1] = fmaf(v1, v1, q[t * 2 + 1]);
            }
        }
    }
    const int pb = blockIdx.y * C + c8;
#pragma unroll
    for (int j = 0; j < 8; j++) { g_psum[pb + j] = s[j]; g_psumsq[pb + j] = q[j]; }
}

__global__ void col_stats_finalize(const float* __restrict__ gamma, const float* __restrict__ bnb,
                                   float* __restrict__ scale, float* __restrict__ shift, int C) {
    int c = blockIdx.x * 256 + threadIdx.x;
    double s = 0, q = 0;
    for (int i = 0; i < RSX; i++) { s += (double)g_psum[(size_t)i * C + c]; q += (double)g_psumsq[(size_t)i * C + c]; }
    double mu  = s * (1.0 / NROWS);
    double var = q * (1.0 / NROWS) - mu * mu;
    float a = rsqrtf((float)var + 1e-5f) * gamma[c];
    scale[c] = a;
    shift[c] = bnb[c] - (float)mu * a;
}

__global__ void fold_split(const float* __restrict__ W, const float* __restrict__ bias,
                           const float* __restrict__ scale, const float* __restrict__ shift,
                           __nv_bfloat16* __restrict__ Whi, __nv_bfloat16* __restrict__ Wlo,
                           float* __restrict__ bf, int K) {
    int j = blockIdx.x;
    const float* Wr = W + (size_t)j * K;
    float dot = 0.f;
    for (int k = threadIdx.x; k < K; k += 256) {
        float w = Wr[k];
        float wf = w * scale[k];
        __nv_bfloat16 h = __float2bfloat16(wf);
        Whi[(size_t)j * K + k] = h;
        Wlo[(size_t)j * K + k] = __float2bfloat16(wf - __bfloat162float(h));
        dot += w * shift[k];
    }
    __shared__ float red[256];
    red[threadIdx.x] = dot;
    __syncthreads();
    for (int s = 128; s > 0; s >>= 1) {
        if (threadIdx.x < s) red[threadIdx.x] += red[threadIdx.x + s];
        __syncthreads();
    }
    if (threadIdx.x == 0) bf[j] = bias[j] + red[0];
}

// ---------------- mma.sync GEMM: C = (Ahi+Alo)[M,K] @ (Bhi+Blo)[N,K]^T ----------------
template <bool L2E>
__global__ __launch_bounds__(256, 2)
void gemm_mma(const __nv_bfloat16* __restrict__ Ahi, const __nv_bfloat16* __restrict__ Alo,
              const __nv_bfloat16* __restrict__ Bhi, const __nv_bfloat16* __restrict__ Blo,
              const float* __restrict__ bias, const float* __restrict__ Y,
              const float* __restrict__ betap, float* __restrict__ Cout,
              __nv_bfloat16* __restrict__ Chi, __nv_bfloat16* __restrict__ Clo,
              int K, int Nout) {
    extern __shared__ __align__(1024) char smem[];
    const uint32_t sb = smem_u32(smem);
    const int tid  = threadIdx.x;
    const int wid  = tid >> 5;
    const int lane = tid & 31;
    const int wm   = (wid >> 2) * 64;      // warp m offset in tile
    const int wn   = (wid & 3) * 32;       // warp n offset in tile

    const int ldb = K * 2;  // row stride, bytes
    const char* gAhi = (const char*)(Ahi + (size_t)(blockIdx.y * BM) * K);
    const char* gAlo = (const char*)(Alo + (size_t)(blockIdx.y * BM) * K);
    const char* gBhi = (const char*)(Bhi + (size_t)(blockIdx.x * BN) * K);
    const char* gBlo = (const char*)(Blo + (size_t)(blockIdx.x * BN) * K);
    const int NC = K / BKC;

    auto load_stage = [&](int ch, int st) {
        uint32_t s0 = sb + st * STAGE;
        size_t kb = (size_t)ch * 64;
#pragma unroll
        for (int t = 0; t < 2; t++) {
            int o = tid + t * 256;
            int r = o >> 2, c = o & 3;
            uint32_t so = (uint32_t)r * 64 + ((uint32_t)(c ^ ((r >> 1) & 3)) << 4);
            size_t go = (size_t)r * ldb + kb + c * 16;
            cp16(s0 + so,         gAhi + go);
            cp16(s0 + 8192 + so,  gAlo + go);
            cp16(s0 + 16384 + so, gBhi + go);
            cp16(s0 + 24576 + so, gBlo + go);
        }
    };

    float acc[4][4][4];
#pragma unroll
    for (int i = 0; i < 4; i++)
#pragma unroll
        for (int j = 0; j < 4; j++)
#pragma unroll
            for (int r = 0; r < 4; r++) acc[i][j][r] = 0.f;

    // prologue: fill NSTAGE-1 stages
#pragma unroll
    for (int s = 0; s < NSTAGE - 1; s++) { load_stage(s, s); cp_commit(); }

    for (int i = 0; i < NC; i++) {
        cp_wait1();
        __syncthreads();
        // issue next-stage loads FIRST so they overlap this chunk's compute
        if (i + NSTAGE - 1 < NC) { load_stage(i + NSTAGE - 1, (i + NSTAGE - 1) % NSTAGE); }
        cp_commit();

        const uint32_t st = sb + (i % NSTAGE) * STAGE;
        const uint32_t sAhi = st, sAlo = st + 8192, sBhi = st + 16384, sBlo = st + 24576;

#pragma unroll
        for (int s = 0; s < 2; s++) {
            uint32_t af[4][4], bfr[2][4], tf[4][4];
            const int ar = wm + (lane & 15);
            const int ac = s * 2 + (lane >> 4);
            const int br = wn + (lane & 7) + ((lane & 16) ? 8 : 0);
            const int bc = s * 2 + ((lane >> 3) & 1);
            // hi A, hi B
#pragma unroll
            for (int mi = 0; mi < 4; mi++)
                ldsm_x4(af[mi][0], af[mi][1], af[mi][2], af[mi][3], tswz(sAhi, ar + mi * 16, ac));
#pragma unroll
            for (int nj = 0; nj < 2; nj++)
                ldsm_x4(bfr[nj][0], bfr[nj][1], bfr[nj][2], bfr[nj][3], tswz(sBhi, br + nj * 16, bc));
#pragma unroll
            for (int mi = 0; mi < 4; mi++)
#pragma unroll
                for (int jj = 0; jj < 4; jj++)
                    mma16816(acc[mi][jj], af[mi], bfr[jj >> 1][(jj & 1) * 2], bfr[jj >> 1][(jj & 1) * 2 + 1]);
            // lo A x hi B
#pragma unroll
            for (int mi = 0; mi < 4; mi++)
                ldsm_x4(tf[mi][0], tf[mi][1], tf[mi][2], tf[mi][3], tswz(sAlo, ar + mi * 16, ac));
#pragma unroll
            for (int mi = 0; mi < 4; mi++)
#pragma unroll
                for (int jj = 0; jj < 4; jj++)
                    mma16816(acc[mi][jj], tf[mi], bfr[jj >> 1][(jj & 1) * 2], bfr[jj >> 1][(jj & 1) * 2 + 1]);
            // hi A x lo B (overwrite B regs)
#pragma unroll
            for (int nj = 0; nj < 2; nj++)
                ldsm_x4(bfr[nj][0], bfr[nj][1], bfr[nj][2], bfr[nj][3], tswz(sBlo, br + nj * 16, bc));
#pragma unroll
            for (int mi = 0; mi < 4; mi++)
#pragma unroll
                for (int jj = 0; jj < 4; jj++)
                    mma16816(acc[mi][jj], af[mi], bfr[jj >> 1][(jj & 1) * 2], bfr[jj >> 1][(jj & 1) * 2 + 1]);
        }
    }
    cp_wait0();

    // ---- epilogue ----
    const int bm_ = blockIdx.y * BM, bn_ = blockIdx.x * BN;
    const float bsc = L2E ? __ldg(betap) : 0.f;
#pragma unroll
    for (int mi = 0; mi < 4; mi++) {
#pragma unroll
        for (int jj = 0; jj < 4; jj++) {
            const int row0 = bm_ + wm + mi * 16 + (lane >> 2);
            const int col  = bn_ + wn + jj * 8 + 2 * (lane & 3);
            const float bb0 = __ldg(&bias[col]), bb1 = __ldg(&bias[col + 1]);
#pragma unroll
            for (int h = 0; h < 2; h++) {
                const int row = row0 + h * 8;
                float v0 = acc[mi][jj][h * 2 + 0] + bb0;
                float v1 = acc[mi][jj][h * 2 + 1] + bb1;
                if (!L2E) {
                    v0 = fmaxf(v0, 0.f); v1 = fmaxf(v1, 0.f);
                    __nv_bfloat16 h0 = __float2bfloat16(v0);
                    __nv_bfloat16 h1 = __float2bfloat16(v1);
                    __nv_bfloat162 hv; hv.x = h0; hv.y = h1;
                    __nv_bfloat162 lv;
                    lv.x = __float2bfloat16(v0 - __bfloat162float(h0));
                    lv.y = __float2bfloat16(v1 - __bfloat162float(h1));
                    *(__nv_bfloat162*)(Chi + (size_t)row * Nout + col) = hv;
                    *(__nv_bfloat162*)(Clo + (size_t)row * Nout + col) = lv;
                } else {
                    const float2 yv = *(const float2*)(Y + (size_t)row * Nout + col);
                    float2 o;
                    o.x = v0 + bsc * yv.x;
                    o.y = v1 + bsc * yv.y;
                    *(float2*)(Cout + (size_t)row * Nout + col) = o;
                }
            }
        }
    }
}

// ---------------- launch ----------------
extern "C" void kernel_launch(void* const* d_in, const int* in_sizes, int n_in,
                              void* d_out, int out_size) {
    const float* x    = (const float*)d_in[0];
    const float* y    = (const float*)d_in[1];
    const float* W1   = (const float*)d_in[2];
    const float* b1   = (const float*)d_in[3];
    const float* W2   = (const float*)d_in[4];
    const float* b2   = (const float*)d_in[5];
    const float* bn1g = (const float*)d_in[6];
    const float* bn1b = (const float*)d_in[7];
    const float* bn2g = (const float*)d_in[8];
    const float* bn2b = (const float*)d_in[9];
    const float* beta = (const float*)d_in[10];
    float* out = (float*)d_out;

    __nv_bfloat16 *xhi, *xlo, *h1hi, *h1lo, *w1hi, *w1lo, *w2hi, *w2lo;
    float *b1f, *b2f, *sc1, *sh1, *sc2, *sh2;
    cudaGetSymbolAddress((void**)&xhi,  g_xhi);
    cudaGetSymbolAddress((void**)&xlo,  g_xlo);
    cudaGetSymbolAddress((void**)&h1hi, g_h1hi);
    cudaGetSymbolAddress((void**)&h1lo, g_h1lo);
    cudaGetSymbolAddress((void**)&w1hi, g_w1hi);
    cudaGetSymbolAddress((void**)&w1lo, g_w1lo);
    cudaGetSymbolAddress((void**)&w2hi, g_w2hi);
    cudaGetSymbolAddress((void**)&w2lo, g_w2lo);
    cudaGetSymbolAddress((void**)&b1f,  g_b1f);
    cudaGetSymbolAddress((void**)&b2f,  g_b2f);
    cudaGetSymbolAddress((void**)&sc1,  g_scale1);
    cudaGetSymbolAddress((void**)&sh1,  g_shift1);
    cudaGetSymbolAddress((void**)&sc2,  g_scale2);
    cudaGetSymbolAddress((void**)&sh2,  g_shift2);

    cudaFuncSetAttribute(gemm_mma<false>, cudaFuncAttributeMaxDynamicSharedMemorySize, SMEM_DYN);
    cudaFuncSetAttribute(gemm_mma<true>,  cudaFuncAttributeMaxDynamicSharedMemorySize, SMEM_DYN);

    // layer 1
    conv_stats_x<<<dim3(NFEAT / 1024, RSX), 256>>>(x, xhi, xlo, NFEAT, NROWS / RSX);
    col_stats_finalize<<<NFEAT / 256, 256>>>(bn1g, bn1b, sc1, sh1, NFEAT);
    fold_split<<<NHID, 256>>>(W1, b1, sc1, sh1, w1hi, w1lo, b1f, NFEAT);
    gemm_mma<false><<<dim3(NHID / BN, NROWS / BM), 256, SMEM_DYN>>>(
        xhi, xlo, w1hi, w1lo, b1f, nullptr, nullptr, nullptr, h1hi, h1lo, NFEAT, NHID);

    // layer 2
    stats_split<<<dim3(NHID / 2048, RSX), 256>>>(h1hi, h1lo, NHID, NROWS / RSX);
    col_stats_finalize<<<NHID / 256, 256>>>(bn2g, bn2b, sc2, sh2, NHID);
    fold_split<<<NCLS, 256>>>(W2, b2, sc2, sh2, w2hi, w2lo, b2f, NHID);
    gemm_mma<true><<<dim3(NCLS / BN, NROWS / BM), 256, SMEM_DYN>>>(
        h1hi, h1lo, w2hi, w2lo, b2f, y, beta, out, nullptr, nullptr, NHID, NCLS);
}

// round 7
// speedup vs baseline: 5.0027x; 1.4158x over previous
#include <cuda_runtime.h>
#include <cuda_fp16.h>
#include <cstdint>

#define NROWS 32768
#define NFEAT 2048
#define NHID  4096
#define NCLS  512
#define RSX   256            // partial-split factor for column stats

// GEMM tiling: 128x128 CTA tile, BK=32, 8 warps (2x4), warp tile 64x32
#define BM 128
#define BN 128
#define BKC 32
#define STAGE 24576          // Ahi 8K + Alo 8K + Bhi 8K
#define NSTAGE 4
#define SMEM_DYN (NSTAGE * STAGE)

// ---------------- device scratch ----------------
__device__ __half g_xhi [(size_t)NROWS * NFEAT];
__device__ __half g_xlo [(size_t)NROWS * NFEAT];
__device__ __half g_h1hi[(size_t)NROWS * NHID];
__device__ __half g_h1lo[(size_t)NROWS * NHID];
__device__ __half g_w1hi[(size_t)NHID  * NFEAT];
__device__ __half g_w2hi[(size_t)NCLS  * NHID];
__device__ float  g_b1f[NHID];
__device__ float  g_b2f[NCLS];
__device__ float  g_scale1[NFEAT], g_shift1[NFEAT];
__device__ float  g_scale2[NHID],  g_shift2[NHID];
__device__ float  g_psum  [(size_t)RSX * NHID];
__device__ float  g_psumsq[(size_t)RSX * NHID];

// ---------------- PTX helpers (family-portable only: sm_80-era) ----------------
__device__ __forceinline__ uint32_t smem_u32(const void* p) {
    uint32_t a;
    asm("{ .reg .u64 t; cvta.to.shared.u64 t, %1; cvt.u32.u64 %0, t; }" : "=r"(a) : "l"(p));
    return a;
}
__device__ __forceinline__ void cp16(uint32_t s, const void* g) {
    asm volatile("cp.async.cg.shared.global [%0], [%1], 16;" :: "r"(s), "l"(g));
}
__device__ __forceinline__ void cp_commit() { asm volatile("cp.async.commit_group;" ::: "memory"); }
__device__ __forceinline__ void cp_wait2()  { asm volatile("cp.async.wait_group 2;" ::: "memory"); }
__device__ __forceinline__ void cp_wait0()  { asm volatile("cp.async.wait_group 0;" ::: "memory"); }

__device__ __forceinline__ void ldsm_x4(uint32_t& d0, uint32_t& d1, uint32_t& d2, uint32_t& d3, uint32_t addr) {
    asm volatile("ldmatrix.sync.aligned.m8n8.x4.shared.b16 {%0,%1,%2,%3}, [%4];"
                 : "=r"(d0), "=r"(d1), "=r"(d2), "=r"(d3) : "r"(addr));
}
__device__ __forceinline__ void mma16816(float* c, const uint32_t* a, uint32_t b0, uint32_t b1) {
    asm volatile("mma.sync.aligned.m16n8k16.row.col.f32.f16.f16.f32 "
                 "{%0,%1,%2,%3}, {%4,%5,%6,%7}, {%8,%9}, {%0,%1,%2,%3};"
                 : "+f"(c[0]), "+f"(c[1]), "+f"(c[2]), "+f"(c[3])
                 : "r"(a[0]), "r"(a[1]), "r"(a[2]), "r"(a[3]), "r"(b0), "r"(b1));
}

// swizzled byte address inside a 128-row x 64B tile (16B chunk granularity).
__device__ __forceinline__ uint32_t tswz(uint32_t base, int r, int c) {
    return base + r * 64 + ((c ^ ((r >> 1) & 3)) << 4);
}

// ---------------- stats / conversion kernels (fp32 partials, wide grids) ----------------
// grid (C/1024, RSX); each thread owns 4 consecutive columns over 128 rows.
__global__ __launch_bounds__(256)
void conv_stats_x(const float* __restrict__ X,
                  __half* __restrict__ Xhi, __half* __restrict__ Xlo,
                  int C, int rowsPer) {
    const int c4 = (blockIdx.x * 256 + threadIdx.x) * 4;
    const size_t base = (size_t)blockIdx.y * rowsPer * C + c4;
    float s0 = 0, s1 = 0, s2 = 0, s3 = 0;
    float q0 = 0, q1 = 0, q2 = 0, q3 = 0;
    for (int r = 0; r < rowsPer; r += 4) {
#pragma unroll
        for (int u = 0; u < 4; u++) {
            const size_t o = base + (size_t)(r + u) * C;
            float4 v = *(const float4*)(X + o);
            s0 += v.x; q0 = fmaf(v.x, v.x, q0);
            s1 += v.y; q1 = fmaf(v.y, v.y, q1);
            s2 += v.z; q2 = fmaf(v.z, v.z, q2);
            s3 += v.w; q3 = fmaf(v.w, v.w, q3);
            __half h0 = __float2half(v.x), h1 = __float2half(v.y);
            __half h2 = __float2half(v.z), h3 = __float2half(v.w);
            __half2 hA = __halves2half2(h0, h1);
            __half2 hB = __halves2half2(h2, h3);
            *(uint2*)(Xhi + o) = make_uint2(*(uint32_t*)&hA, *(uint32_t*)&hB);
            __half2 lA = __halves2half2(__float2half(v.x - __half2float(h0)),
                                        __float2half(v.y - __half2float(h1)));
            __half2 lB = __halves2half2(__float2half(v.z - __half2float(h2)),
                                        __float2half(v.w - __half2float(h3)));
            *(uint2*)(Xlo + o) = make_uint2(*(uint32_t*)&lA, *(uint32_t*)&lB);
        }
    }
    const int pb = blockIdx.y * C + c4;
    g_psum[pb + 0] = s0; g_psum[pb + 1] = s1; g_psum[pb + 2] = s2; g_psum[pb + 3] = s3;
    g_psumsq[pb + 0] = q0; g_psumsq[pb + 1] = q1; g_psumsq[pb + 2] = q2; g_psumsq[pb + 3] = q3;
}

// grid (C/2048, RSX); each thread owns 8 consecutive fp16 columns over 128 rows.
__global__ __launch_bounds__(256)
void stats_split(const __half* __restrict__ Hi,
                 const __half* __restrict__ Lo, int C, int rowsPer) {
    const int c8 = (blockIdx.x * 256 + threadIdx.x) * 8;
    const size_t base = (size_t)blockIdx.y * rowsPer * C + c8;
    float s[8], q[8];
#pragma unroll
    for (int j = 0; j < 8; j++) { s[j] = 0.f; q[j] = 0.f; }
    for (int r = 0; r < rowsPer; r += 4) {
#pragma unroll
        for (int u = 0; u < 4; u++) {
            const size_t o = base + (size_t)(r + u) * C;
            uint4 hv = *(const uint4*)(Hi + o);
            uint4 lv = *(const uint4*)(Lo + o);
            const uint32_t* hp = &hv.x;
            const uint32_t* lp = &lv.x;
#pragma unroll
            for (int t = 0; t < 4; t++) {
                float2 hf = __half22float2(*(const __half2*)&hp[t]);
                float2 lf = __half22float2(*(const __half2*)&lp[t]);
                float v0 = hf.x + lf.x, v1 = hf.y + lf.y;
                s[t * 2 + 0] += v0; q[t * 2 + 0] = fmaf(v0, v0, q[t * 2 + 0]);
                s[t * 2 + 1] += v1; q[t * 2 + 1] = fmaf(v1, v1, q[t * 2 + 1]);
            }
        }
    }
    const int pb = blockIdx.y * C + c8;
#pragma unroll
    for (int j = 0; j < 8; j++) { g_psum[pb + j] = s[j]; g_psumsq[pb + j] = q[j]; }
}

__global__ void col_stats_finalize(const float* __restrict__ gamma, const float* __restrict__ bnb,
                                   float* __restrict__ scale, float* __restrict__ shift, int C) {
    int c = blockIdx.x * 256 + threadIdx.x;
    double s = 0, q = 0;
    for (int i = 0; i < RSX; i++) { s += (double)g_psum[(size_t)i * C + c]; q += (double)g_psumsq[(size_t)i * C + c]; }
    double mu  = s * (1.0 / NROWS);
    double var = q * (1.0 / NROWS) - mu * mu;
    float a = rsqrtf((float)var + 1e-5f) * gamma[c];
    scale[c] = a;
    shift[c] = bnb[c] - (float)mu * a;
}

__global__ void fold_split(const float* __restrict__ W, const float* __restrict__ bias,
                           const float* __restrict__ scale, const float* __restrict__ shift,
                           __half* __restrict__ Whi, float* __restrict__ bf, int K) {
    int j = blockIdx.x;
    const float* Wr = W + (size_t)j * K;
    float dot = 0.f;
    for (int k = threadIdx.x; k < K; k += 256) {
        float w = Wr[k];
        Whi[(size_t)j * K + k] = __float2half(w * scale[k]);
        dot += w * shift[k];
    }
    __shared__ float red[256];
    red[threadIdx.x] = dot;
    __syncthreads();
    for (int s = 128; s > 0; s >>= 1) {
        if (threadIdx.x < s) red[threadIdx.x] += red[threadIdx.x + s];
        __syncthreads();
    }
    if (threadIdx.x == 0) bf[j] = bias[j] + red[0];
}

// ---------------- mma.sync GEMM: C = (Ahi+Alo)[M,K] @ Bhi[N,K]^T  (fp16, 2-pass) --------
template <bool L2E>
__global__ __launch_bounds__(256, 2)
void gemm_mma(const __half* __restrict__ Ahi, const __half* __restrict__ Alo,
              const __half* __restrict__ Bhi,
              const float* __restrict__ bias, const float* __restrict__ Y,
              const float* __restrict__ betap, float* __restrict__ Cout,
              __half* __restrict__ Chi, __half* __restrict__ Clo,
              int K, int Nout) {
    extern __shared__ __align__(1024) char smem[];
    const uint32_t sb = smem_u32(smem);
    const int tid  = threadIdx.x;
    const int wid  = tid >> 5;
    const int lane = tid & 31;
    const int wm   = (wid >> 2) * 64;      // warp m offset in tile
    const int wn   = (wid & 3) * 32;       // warp n offset in tile

    const int ldb = K * 2;  // row stride, bytes
    const char* gAhi = (const char*)(Ahi + (size_t)(blockIdx.y * BM) * K);
    const char* gAlo = (const char*)(Alo + (size_t)(blockIdx.y * BM) * K);
    const char* gBhi = (const char*)(Bhi + (size_t)(blockIdx.x * BN) * K);
    const int NC = K / BKC;

    auto load_stage = [&](int ch, int st) {
        uint32_t s0 = sb + st * STAGE;
        size_t kb = (size_t)ch * 64;
#pragma unroll
        for (int t = 0; t < 2; t++) {
            int o = tid + t * 256;
            int r = o >> 2, c = o & 3;
            uint32_t so = (uint32_t)r * 64 + ((uint32_t)(c ^ ((r >> 1) & 3)) << 4);
            size_t go = (size_t)r * ldb + kb + c * 16;
            cp16(s0 + so,         gAhi + go);
            cp16(s0 + 8192 + so,  gAlo + go);
            cp16(s0 + 16384 + so, gBhi + go);
        }
    };

    float acc[4][4][4];
#pragma unroll
    for (int i = 0; i < 4; i++)
#pragma unroll
        for (int j = 0; j < 4; j++)
#pragma unroll
            for (int r = 0; r < 4; r++) acc[i][j][r] = 0.f;

    // prologue: fill NSTAGE-1 stages
#pragma unroll
    for (int s = 0; s < NSTAGE - 1; s++) { load_stage(s, s); cp_commit(); }

    for (int i = 0; i < NC; i++) {
        cp_wait2();
        __syncthreads();
        // issue next-stage loads FIRST so they overlap this chunk's compute
        if (i + NSTAGE - 1 < NC) { load_stage(i + NSTAGE - 1, (i + NSTAGE - 1) % NSTAGE); }
        cp_commit();

        const uint32_t st = sb + (i % NSTAGE) * STAGE;
        const uint32_t sAhi = st, sAlo = st + 8192, sBhi = st + 16384;

#pragma unroll
        for (int s = 0; s < 2; s++) {
            uint32_t ah[4][4], al[4][4], bh[2][4];
            const int ar = wm + (lane & 15);
            const int ac = s * 2 + (lane >> 4);
            const int br = wn + (lane & 7) + ((lane & 16) ? 8 : 0);
            const int bc = s * 2 + ((lane >> 3) & 1);
#pragma unroll
            for (int mi = 0; mi < 4; mi++)
                ldsm_x4(ah[mi][0], ah[mi][1], ah[mi][2], ah[mi][3], tswz(sAhi, ar + mi * 16, ac));
#pragma unroll
            for (int nj = 0; nj < 2; nj++)
                ldsm_x4(bh[nj][0], bh[nj][1], bh[nj][2], bh[nj][3], tswz(sBhi, br + nj * 16, bc));
            // pass 1: hi A x B
#pragma unroll
            for (int mi = 0; mi < 4; mi++)
#pragma unroll
                for (int jj = 0; jj < 4; jj++)
                    mma16816(acc[mi][jj], ah[mi], bh[jj >> 1][(jj & 1) * 2], bh[jj >> 1][(jj & 1) * 2 + 1]);
            // pass 2: lo A x B
#pragma unroll
            for (int mi = 0; mi < 4; mi++)
                ldsm_x4(al[mi][0], al[mi][1], al[mi][2], al[mi][3], tswz(sAlo, ar + mi * 16, ac));
#pragma unroll
            for (int mi = 0; mi < 4; mi++)
#pragma unroll
                for (int jj = 0; jj < 4; jj++)
                    mma16816(acc[mi][jj], al[mi], bh[jj >> 1][(jj & 1) * 2], bh[jj >> 1][(jj & 1) * 2 + 1]);
        }
    }
    cp_wait0();

    // ---- epilogue ----
    const int bm_ = blockIdx.y * BM, bn_ = blockIdx.x * BN;
    const float bsc = L2E ? __ldg(betap) : 0.f;
#pragma unroll
    for (int mi = 0; mi < 4; mi++) {
#pragma unroll
        for (int jj = 0; jj < 4; jj++) {
            const int row0 = bm_ + wm + mi * 16 + (lane >> 2);
            const int col  = bn_ + wn + jj * 8 + 2 * (lane & 3);
            const float bb0 = __ldg(&bias[col]), bb1 = __ldg(&bias[col + 1]);
#pragma unroll
            for (int h = 0; h < 2; h++) {
                const int row = row0 + h * 8;
                float v0 = acc[mi][jj][h * 2 + 0] + bb0;
                float v1 = acc[mi][jj][h * 2 + 1] + bb1;
                if (!L2E) {
                    v0 = fmaxf(v0, 0.f); v1 = fmaxf(v1, 0.f);
                    __half h0 = __float2half(v0);
                    __half h1 = __float2half(v1);
                    __half2 hv = __halves2half2(h0, h1);
                    __half2 lv = __halves2half2(__float2half(v0 - __half2float(h0)),
                                                __float2half(v1 - __half2float(h1)));
                    *(__half2*)(Chi + (size_t)row * Nout + col) = hv;
                    *(__half2*)(Clo + (size_t)row * Nout + col) = lv;
                } else {
                    const float2 yv = *(const float2*)(Y + (size_t)row * Nout + col);
                    float2 o;
                    o.x = v0 + bsc * yv.x;
                    o.y = v1 + bsc * yv.y;
                    *(float2*)(Cout + (size_t)row * Nout + col) = o;
                }
            }
        }
    }
}

// ---------------- launch ----------------
extern "C" void kernel_launch(void* const* d_in, const int* in_sizes, int n_in,
                              void* d_out, int out_size) {
    const float* x    = (const float*)d_in[0];
    const float* y    = (const float*)d_in[1];
    const float* W1   = (const float*)d_in[2];
    const float* b1   = (const float*)d_in[3];
    const float* W2   = (const float*)d_in[4];
    const float* b2   = (const float*)d_in[5];
    const float* bn1g = (const float*)d_in[6];
    const float* bn1b = (const float*)d_in[7];
    const float* bn2g = (const float*)d_in[8];
    const float* bn2b = (const float*)d_in[9];
    const float* beta = (const float*)d_in[10];
    float* out = (float*)d_out;

    __half *xhi, *xlo, *h1hi, *h1lo, *w1hi, *w2hi;
    float *b1f, *b2f, *sc1, *sh1, *sc2, *sh2;
    cudaGetSymbolAddress((void**)&xhi,  g_xhi);
    cudaGetSymbolAddress((void**)&xlo,  g_xlo);
    cudaGetSymbolAddress((void**)&h1hi, g_h1hi);
    cudaGetSymbolAddress((void**)&h1lo, g_h1lo);
    cudaGetSymbolAddress((void**)&w1hi, g_w1hi);
    cudaGetSymbolAddress((void**)&w2hi, g_w2hi);
    cudaGetSymbolAddress((void**)&b1f,  g_b1f);
    cudaGetSymbolAddress((void**)&b2f,  g_b2f);
    cudaGetSymbolAddress((void**)&sc1,  g_scale1);
    cudaGetSymbolAddress((void**)&sh1,  g_shift1);
    cudaGetSymbolAddress((void**)&sc2,  g_scale2);
    cudaGetSymbolAddress((void**)&sh2,  g_shift2);

    cudaFuncSetAttribute(gemm_mma<false>, cudaFuncAttributeMaxDynamicSharedMemorySize, SMEM_DYN);
    cudaFuncSetAttribute(gemm_mma<true>,  cudaFuncAttributeMaxDynamicSharedMemorySize, SMEM_DYN);

    // layer 1
    conv_stats_x<<<dim3(NFEAT / 1024, RSX), 256>>>(x, xhi, xlo, NFEAT, NROWS / RSX);
    col_stats_finalize<<<NFEAT / 256, 256>>>(bn1g, bn1b, sc1, sh1, NFEAT);
    fold_split<<<NHID, 256>>>(W1, b1, sc1, sh1, w1hi, b1f, NFEAT);
    gemm_mma<false><<<dim3(NHID / BN, NROWS / BM), 256, SMEM_DYN>>>(
        xhi, xlo, w1hi, b1f, nullptr, nullptr, nullptr, h1hi, h1lo, NFEAT, NHID);

    // layer 2
    stats_split<<<dim3(NHID / 2048, RSX), 256>>>(h1hi, h1lo, NHID, NROWS / RSX);
    col_stats_finalize<<<NHID / 256, 256>>>(bn2g, bn2b, sc2, sh2, NHID);
    fold_split<<<NCLS, 256>>>(W2, b2, sc2, sh2, w2hi, b2f, NHID);
    gemm_mma<true><<<dim3(NCLS / BN, NROWS / BM), 256, SMEM_DYN>>>(
        h1hi, h1lo, w2hi, b2f, y, beta, out, nullptr, nullptr, NHID, NCLS);
}

// round 9
// speedup vs baseline: 8.8410x; 1.7672x over previous
#include <cuda_runtime.h>
#include <cuda_fp16.h>
#include <cstdint>

#define NROWS 32768
#define NFEAT 2048
#define NHID  4096
#define NCLS  512
#define RSX   256            // partial-split factor for column stats

// GEMM tiling: 128x128 CTA tile, BK=32, 8 warps (2x4), warp tile 64x32
#define BM 128
#define BN 128
#define BKC 32
#define STAGE 16384          // A 8K + B 8K
#define NSTAGE 5
#define SMEM_DYN (NSTAGE * STAGE)

// ---------------- device scratch ----------------
__device__ __half g_xh [(size_t)NROWS * NFEAT];
__device__ __half g_h1 [(size_t)NROWS * NHID];
__device__ __half g_w1h[(size_t)NHID  * NFEAT];
__device__ __half g_w2h[(size_t)NCLS  * NHID];
__device__ float  g_b1f[NHID];
__device__ float  g_b2f[NCLS];
__device__ float  g_scale1[NFEAT], g_shift1[NFEAT];
__device__ float  g_scale2[NHID],  g_shift2[NHID];
__device__ float  g_psum  [(size_t)RSX * NHID];
__device__ float  g_psumsq[(size_t)RSX * NHID];

// ---------------- PTX helpers (family-portable only: sm_80-era) ----------------
__device__ __forceinline__ uint32_t smem_u32(const void* p) {
    uint32_t a;
    asm("{ .reg .u64 t; cvta.to.shared.u64 t, %1; cvt.u32.u64 %0, t; }" : "=r"(a) : "l"(p));
    return a;
}
__device__ __forceinline__ void cp16(uint32_t s, const void* g) {
    asm volatile("cp.async.cg.shared.global [%0], [%1], 16;" :: "r"(s), "l"(g));
}
__device__ __forceinline__ void cp_commit() { asm volatile("cp.async.commit_group;" ::: "memory"); }
__device__ __forceinline__ void cp_wait3()  { asm volatile("cp.async.wait_group 3;" ::: "memory"); }
__device__ __forceinline__ void cp_wait0()  { asm volatile("cp.async.wait_group 0;" ::: "memory"); }

__device__ __forceinline__ void ldsm_x4(uint32_t& d0, uint32_t& d1, uint32_t& d2, uint32_t& d3, uint32_t addr) {
    asm volatile("ldmatrix.sync.aligned.m8n8.x4.shared.b16 {%0,%1,%2,%3}, [%4];"
                 : "=r"(d0), "=r"(d1), "=r"(d2), "=r"(d3) : "r"(addr));
}
__device__ __forceinline__ void mma16816(float* c, const uint32_t* a, uint32_t b0, uint32_t b1) {
    asm volatile("mma.sync.aligned.m16n8k16.row.col.f32.f16.f16.f32 "
                 "{%0,%1,%2,%3}, {%4,%5,%6,%7}, {%8,%9}, {%0,%1,%2,%3};"
                 : "+f"(c[0]), "+f"(c[1]), "+f"(c[2]), "+f"(c[3])
                 : "r"(a[0]), "r"(a[1]), "r"(a[2]), "r"(a[3]), "r"(b0), "r"(b1));
}

// swizzled byte address inside a 128-row x 64B tile (16B chunk granularity).
__device__ __forceinline__ uint32_t tswz(uint32_t base, int r, int c) {
    return base + r * 64 + ((c ^ ((r >> 1) & 3)) << 4);
}

// ---------------- stats / conversion kernels (fp32 partials, wide grids) ----------------
// grid (C/1024, RSX); each thread owns 4 consecutive columns over 128 rows.
__global__ __launch_bounds__(256)
void conv_stats_x(const float* __restrict__ X, __half* __restrict__ Xh,
                  int C, int rowsPer) {
    const int c4 = (blockIdx.x * 256 + threadIdx.x) * 4;
    const size_t base = (size_t)blockIdx.y * rowsPer * C + c4;
    float s0 = 0, s1 = 0, s2 = 0, s3 = 0;
    float q0 = 0, q1 = 0, q2 = 0, q3 = 0;
    for (int r = 0; r < rowsPer; r += 4) {
#pragma unroll
        for (int u = 0; u < 4; u++) {
            const size_t o = base + (size_t)(r + u) * C;
            float4 v = *(const float4*)(X + o);
            s0 += v.x; q0 = fmaf(v.x, v.x, q0);
            s1 += v.y; q1 = fmaf(v.y, v.y, q1);
            s2 += v.z; q2 = fmaf(v.z, v.z, q2);
            s3 += v.w; q3 = fmaf(v.w, v.w, q3);
            __half2 hA = __halves2half2(__float2half(v.x), __float2half(v.y));
            __half2 hB = __halves2half2(__float2half(v.z), __float2half(v.w));
            *(uint2*)(Xh + o) = make_uint2(*(uint32_t*)&hA, *(uint32_t*)&hB);
        }
    }
    const int pb = blockIdx.y * C + c4;
    g_psum[pb + 0] = s0; g_psum[pb + 1] = s1; g_psum[pb + 2] = s2; g_psum[pb + 3] = s3;
    g_psumsq[pb + 0] = q0; g_psumsq[pb + 1] = q1; g_psumsq[pb + 2] = q2; g_psumsq[pb + 3] = q3;
}

// grid (C/2048, RSX); each thread owns 8 consecutive fp16 columns over 128 rows.
__global__ __launch_bounds__(256)
void stats_h(const __half* __restrict__ H, int C, int rowsPer) {
    const int c8 = (blockIdx.x * 256 + threadIdx.x) * 8;
    const size_t base = (size_t)blockIdx.y * rowsPer * C + c8;
    float s[8], q[8];
#pragma unroll
    for (int j = 0; j < 8; j++) { s[j] = 0.f; q[j] = 0.f; }
    for (int r = 0; r < rowsPer; r += 4) {
#pragma unroll
        for (int u = 0; u < 4; u++) {
            const size_t o = base + (size_t)(r + u) * C;
            uint4 hv = *(const uint4*)(H + o);
            const uint32_t* hp = &hv.x;
#pragma unroll
            for (int t = 0; t < 4; t++) {
                float2 hf = __half22float2(*(const __half2*)&hp[t]);
                s[t * 2 + 0] += hf.x; q[t * 2 + 0] = fmaf(hf.x, hf.x, q[t * 2 + 0]);
                s[t * 2 + 1] += hf.y; q[t * 2 + 1] = fmaf(hf.y, hf.y, q[t * 2 + 1]);
            }
        }
    }
    const int pb = blockIdx.y * C + c8;
#pragma unroll
    for (int j = 0; j < 8; j++) { g_psum[pb + j] = s[j]; g_psumsq[pb + j] = q[j]; }
}

__global__ void col_stats_finalize(const float* __restrict__ gamma, const float* __restrict__ bnb,
                                   float* __restrict__ scale, float* __restrict__ shift, int C) {
    int c = blockIdx.x * 256 + threadIdx.x;
    double s = 0, q = 0;
    for (int i = 0; i < RSX; i++) { s += (double)g_psum[(size_t)i * C + c]; q += (double)g_psumsq[(size_t)i * C + c]; }
    double mu  = s * (1.0 / NROWS);
    double var = q * (1.0 / NROWS) - mu * mu;
    float a = rsqrtf((float)var + 1e-5f) * gamma[c];
    scale[c] = a;
    shift[c] = bnb[c] - (float)mu * a;
}

__global__ void fold_split(const float* __restrict__ W, const float* __restrict__ bias,
                           const float* __restrict__ scale, const float* __restrict__ shift,
                           __half* __restrict__ Wh, float* __restrict__ bf, int K) {
    int j = blockIdx.x;
    const float* Wr = W + (size_t)j * K;
    float dot = 0.f;
    for (int k = threadIdx.x; k < K; k += 256) {
        float w = Wr[k];
        Wh[(size_t)j * K + k] = __float2half(w * scale[k]);
        dot += w * shift[k];
    }
    __shared__ float red[256];
    red[threadIdx.x] = dot;
    __syncthreads();
    for (int s = 128; s > 0; s >>= 1) {
        if (threadIdx.x < s) red[threadIdx.x] += red[threadIdx.x + s];
        __syncthreads();
    }
    if (threadIdx.x == 0) bf[j] = bias[j] + red[0];
}

// ---------------- mma.sync GEMM: C = A[M,K] @ B[N,K]^T  (fp16, single-pass) ----------------
template <bool L2E>
__global__ __launch_bounds__(256, 2)
void gemm_mma(const __half* __restrict__ A, const __half* __restrict__ B,
              const float* __restrict__ bias, const float* __restrict__ Y,
              const float* __restrict__ betap, float* __restrict__ Cout,
              __half* __restrict__ Ch, int K, int Nout) {
    extern __shared__ __align__(1024) char smem[];
    const uint32_t sb = smem_u32(smem);
    const int tid  = threadIdx.x;
    const int wid  = tid >> 5;
    const int lane = tid & 31;
    const int wm   = (wid >> 2) * 64;      // warp m offset in tile
    const int wn   = (wid & 3) * 32;       // warp n offset in tile

    const int ldb = K * 2;  // row stride, bytes
    const char* gA = (const char*)(A + (size_t)(blockIdx.y * BM) * K);
    const char* gB = (const char*)(B + (size_t)(blockIdx.x * BN) * K);
    const int NC = K / BKC;

    auto load_stage = [&](int ch, int st) {
        uint32_t s0 = sb + st * STAGE;
        size_t kb = (size_t)ch * 64;
#pragma unroll
        for (int t = 0; t < 2; t++) {
            int o = tid + t * 256;
            int r = o >> 2, c = o & 3;
            uint32_t so = (uint32_t)r * 64 + ((uint32_t)(c ^ ((r >> 1) & 3)) << 4);
            size_t go = (size_t)r * ldb + kb + c * 16;
            cp16(s0 + so,        gA + go);
            cp16(s0 + 8192 + so, gB + go);
        }
    };

    float acc[4][4][4];
#pragma unroll
    for (int i = 0; i < 4; i++)
#pragma unroll
        for (int j = 0; j < 4; j++)
#pragma unroll
            for (int r = 0; r < 4; r++) acc[i][j][r] = 0.f;

    // prologue: fill NSTAGE-1 stages
#pragma unroll
    for (int s = 0; s < NSTAGE - 1; s++) { load_stage(s, s); cp_commit(); }

    for (int i = 0; i < NC; i++) {
        cp_wait3();
        __syncthreads();
        // issue next-stage loads FIRST so they overlap this chunk's compute
        if (i + NSTAGE - 1 < NC) { load_stage(i + NSTAGE - 1, (i + NSTAGE - 1) % NSTAGE); }
        cp_commit();

        const uint32_t st = sb + (i % NSTAGE) * STAGE;
        const uint32_t sA = st, sB = st + 8192;

#pragma unroll
        for (int s = 0; s < 2; s++) {
            uint32_t ah[4][4], bh[2][4];
            const int ar = wm + (lane & 15);
            const int ac = s * 2 + (lane >> 4);
            const int br = wn + (lane & 7) + ((lane & 16) ? 8 : 0);
            const int bc = s * 2 + ((lane >> 3) & 1);
#pragma unroll
            for (int mi = 0; mi < 4; mi++)
                ldsm_x4(ah[mi][0], ah[mi][1], ah[mi][2], ah[mi][3], tswz(sA, ar + mi * 16, ac));
#pragma unroll
            for (int nj = 0; nj < 2; nj++)
                ldsm_x4(bh[nj][0], bh[nj][1], bh[nj][2], bh[nj][3], tswz(sB, br + nj * 16, bc));
#pragma unroll
            for (int mi = 0; mi < 4; mi++)
#pragma unroll
                for (int jj = 0; jj < 4; jj++)
                    mma16816(acc[mi][jj], ah[mi], bh[jj >> 1][(jj & 1) * 2], bh[jj >> 1][(jj & 1) * 2 + 1]);
        }
    }
    cp_wait0();

    // ---- epilogue ----
    const int bm_ = blockIdx.y * BM, bn_ = blockIdx.x * BN;
    const float bsc = L2E ? __ldg(betap) : 0.f;
#pragma unroll
    for (int mi = 0; mi < 4; mi++) {
#pragma unroll
        for (int jj = 0; jj < 4; jj++) {
            const int row0 = bm_ + wm + mi * 16 + (lane >> 2);
            const int col  = bn_ + wn + jj * 8 + 2 * (lane & 3);
            const float bb0 = __ldg(&bias[col]), bb1 = __ldg(&bias[col + 1]);
#pragma unroll
            for (int h = 0; h < 2; h++) {
                const int row = row0 + h * 8;
                float v0 = acc[mi][jj][h * 2 + 0] + bb0;
                float v1 = acc[mi][jj][h * 2 + 1] + bb1;
                if (!L2E) {
                    v0 = fmaxf(v0, 0.f); v1 = fmaxf(v1, 0.f);
                    __half2 hv = __halves2half2(__float2half(v0), __float2half(v1));
                    *(__half2*)(Ch + (size_t)row * Nout + col) = hv;
                } else {
                    const float2 yv = *(const float2*)(Y + (size_t)row * Nout + col);
                    float2 o;
                    o.x = v0 + bsc * yv.x;
                    o.y = v1 + bsc * yv.y;
                    *(float2*)(Cout + (size_t)row * Nout + col) = o;
                }
            }
        }
    }
}

// ---------------- launch ----------------
extern "C" void kernel_launch(void* const* d_in, const int* in_sizes, int n_in,
                              void* d_out, int out_size) {
    const float* x    = (const float*)d_in[0];
    const float* y    = (const float*)d_in[1];
    const float* W1   = (const float*)d_in[2];
    const float* b1   = (const float*)d_in[3];
    const float* W2   = (const float*)d_in[4];
    const float* b2   = (const float*)d_in[5];
    const float* bn1g = (const float*)d_in[6];
    const float* bn1b = (const float*)d_in[7];
    const float* bn2g = (const float*)d_in[8];
    const float* bn2b = (const float*)d_in[9];
    const float* beta = (const float*)d_in[10];
    float* out = (float*)d_out;

    __half *xh, *h1, *w1h, *w2h;
    float *b1f, *b2f, *sc1, *sh1, *sc2, *sh2;
    cudaGetSymbolAddress((void**)&xh,  g_xh);
    cudaGetSymbolAddress((void**)&h1,  g_h1);
    cudaGetSymbolAddress((void**)&w1h, g_w1h);
    cudaGetSymbolAddress((void**)&w2h, g_w2h);
    cudaGetSymbolAddress((void**)&b1f, g_b1f);
    cudaGetSymbolAddress((void**)&b2f, g_b2f);
    cudaGetSymbolAddress((void**)&sc1, g_scale1);
    cudaGetSymbolAddress((void**)&sh1, g_shift1);
    cudaGetSymbolAddress((void**)&sc2, g_scale2);
    cudaGetSymbolAddress((void**)&sh2, g_shift2);

    cudaFuncSetAttribute(gemm_mma<false>, cudaFuncAttributeMaxDynamicSharedMemorySize, SMEM_DYN);
    cudaFuncSetAttribute(gemm_mma<true>,  cudaFuncAttributeMaxDynamicSharedMemorySize, SMEM_DYN);

    // layer 1
    conv_stats_x<<<dim3(NFEAT / 1024, RSX), 256>>>(x, xh, NFEAT, NROWS / RSX);
    col_stats_finalize<<<NFEAT / 256, 256>>>(bn1g, bn1b, sc1, sh1, NFEAT);
    fold_split<<<NHID, 256>>>(W1, b1, sc1, sh1, w1h, b1f, NFEAT);
    gemm_mma<false><<<dim3(NHID / BN, NROWS / BM), 256, SMEM_DYN>>>(
        xh, w1h, b1f, nullptr, nullptr, nullptr, h1, NFEAT, NHID);

    // layer 2
    stats_h<<<dim3(NHID / 2048, RSX), 256>>>(h1, NHID, NROWS / RSX);
    col_stats_finalize<<<NHID / 256, 256>>>(bn2g, bn2b, sc2, sh2, NHID);
    fold_split<<<NCLS, 256>>>(W2, b2, sc2, sh2, w2h, b2f, NHID);
    gemm_mma<true><<<dim3(NCLS / BN, NROWS / BM), 256, SMEM_DYN>>>(
        h1, w2h, b2f, y, beta, out, nullptr, NHID, NCLS);
}

// round 10
// speedup vs baseline: 9.5243x; 1.0773x over previous
#include <cuda_runtime.h>
#include <cuda_fp16.h>
#include <cstdint>

#define NROWS 32768
#define NFEAT 2048
#define NHID  4096
#define NCLS  512
#define RSX   256            // partial-split factor for column stats

// GEMM tiling: 128x128 CTA tile, BKC=64, 8 warps (2x4), warp tile 64x32
#define BM 128
#define BN 128
#define BKC 64
#define STAGE 32768          // A 16K + B 16K (128B rows, SW128 swizzle)
#define NSTAGE 3
#define SMEM_DYN (NSTAGE * STAGE)

// ---------------- device scratch ----------------
__device__ __half g_xh [(size_t)NROWS * NFEAT];
__device__ __half g_h1 [(size_t)NROWS * NHID];
__device__ __half g_w1h[(size_t)NHID  * NFEAT];
__device__ __half g_w2h[(size_t)NCLS  * NHID];
__device__ float  g_b1f[NHID];
__device__ float  g_b2f[NCLS];
__device__ float  g_scale1[NFEAT], g_shift1[NFEAT];
__device__ float  g_scale2[NHID],  g_shift2[NHID];
__device__ float  g_psum  [(size_t)RSX * NHID];
__device__ float  g_psumsq[(size_t)RSX * NHID];

// ---------------- PTX helpers (family-portable only: sm_80-era) ----------------
__device__ __forceinline__ uint32_t smem_u32(const void* p) {
    uint32_t a;
    asm("{ .reg .u64 t; cvta.to.shared.u64 t, %1; cvt.u32.u64 %0, t; }" : "=r"(a) : "l"(p));
    return a;
}
__device__ __forceinline__ void cp16(uint32_t s, const void* g) {
    asm volatile("cp.async.cg.shared.global [%0], [%1], 16;" :: "r"(s), "l"(g));
}
__device__ __forceinline__ void cp_commit() { asm volatile("cp.async.commit_group;" ::: "memory"); }
__device__ __forceinline__ void cp_wait1()  { asm volatile("cp.async.wait_group 1;" ::: "memory"); }
__device__ __forceinline__ void cp_wait0()  { asm volatile("cp.async.wait_group 0;" ::: "memory"); }

__device__ __forceinline__ void ldsm_x4(uint32_t& d0, uint32_t& d1, uint32_t& d2, uint32_t& d3, uint32_t addr) {
    asm volatile("ldmatrix.sync.aligned.m8n8.x4.shared.b16 {%0,%1,%2,%3}, [%4];"
                 : "=r"(d0), "=r"(d1), "=r"(d2), "=r"(d3) : "r"(addr));
}
__device__ __forceinline__ void mma16816(float* c, const uint32_t* a, uint32_t b0, uint32_t b1) {
    asm volatile("mma.sync.aligned.m16n8k16.row.col.f32.f16.f16.f32 "
                 "{%0,%1,%2,%3}, {%4,%5,%6,%7}, {%8,%9}, {%0,%1,%2,%3};"
                 : "+f"(c[0]), "+f"(c[1]), "+f"(c[2]), "+f"(c[3])
                 : "r"(a[0]), "r"(a[1]), "r"(a[2]), "r"(a[3]), "r"(b0), "r"(b1));
}

// SW128 swizzle inside a 128B-row tile: 16B chunk column XORed with (row & 7).
// ldmatrix phases (8 rows, fixed chunk col) hit 8 distinct bank groups.
__device__ __forceinline__ uint32_t tswz128(uint32_t base, int r, int c) {
    return base + r * 128 + ((c ^ (r & 7)) << 4);
}

// ---------------- stats / conversion kernels (fp32 partials, wide grids) ----------------
// grid (C/1024, RSX); each thread owns 4 consecutive columns over 128 rows.
__global__ __launch_bounds__(256)
void conv_stats_x(const float* __restrict__ X, __half* __restrict__ Xh,
                  int C, int rowsPer) {
    const int c4 = (blockIdx.x * 256 + threadIdx.x) * 4;
    const size_t base = (size_t)blockIdx.y * rowsPer * C + c4;
    float s0 = 0, s1 = 0, s2 = 0, s3 = 0;
    float q0 = 0, q1 = 0, q2 = 0, q3 = 0;
    for (int r = 0; r < rowsPer; r += 4) {
#pragma unroll
        for (int u = 0; u < 4; u++) {
            const size_t o = base + (size_t)(r + u) * C;
            float4 v = *(const float4*)(X + o);
            s0 += v.x; q0 = fmaf(v.x, v.x, q0);
            s1 += v.y; q1 = fmaf(v.y, v.y, q1);
            s2 += v.z; q2 = fmaf(v.z, v.z, q2);
            s3 += v.w; q3 = fmaf(v.w, v.w, q3);
            __half2 hA = __halves2half2(__float2half(v.x), __float2half(v.y));
            __half2 hB = __halves2half2(__float2half(v.z), __float2half(v.w));
            *(uint2*)(Xh + o) = make_uint2(*(uint32_t*)&hA, *(uint32_t*)&hB);
        }
    }
    const int pb = blockIdx.y * C + c4;
    g_psum[pb + 0] = s0; g_psum[pb + 1] = s1; g_psum[pb + 2] = s2; g_psum[pb + 3] = s3;
    g_psumsq[pb + 0] = q0; g_psumsq[pb + 1] = q1; g_psumsq[pb + 2] = q2; g_psumsq[pb + 3] = q3;
}

// grid (C/2048, RSX); each thread owns 8 consecutive fp16 columns over 128 rows.
__global__ __launch_bounds__(256)
void stats_h(const __half* __restrict__ H, int C, int rowsPer) {
    const int c8 = (blockIdx.x * 256 + threadIdx.x) * 8;
    const size_t base = (size_t)blockIdx.y * rowsPer * C + c8;
    float s[8], q[8];
#pragma unroll
    for (int j = 0; j < 8; j++) { s[j] = 0.f; q[j] = 0.f; }
    for (int r = 0; r < rowsPer; r += 4) {
#pragma unroll
        for (int u = 0; u < 4; u++) {
            const size_t o = base + (size_t)(r + u) * C;
            uint4 hv = *(const uint4*)(H + o);
            const uint32_t* hp = &hv.x;
#pragma unroll
            for (int t = 0; t < 4; t++) {
                float2 hf = __half22float2(*(const __half2*)&hp[t]);
                s[t * 2 + 0] += hf.x; q[t * 2 + 0] = fmaf(hf.x, hf.x, q[t * 2 + 0]);
                s[t * 2 + 1] += hf.y; q[t * 2 + 1] = fmaf(hf.y, hf.y, q[t * 2 + 1]);
            }
        }
    }
    const int pb = blockIdx.y * C + c8;
#pragma unroll
    for (int j = 0; j < 8; j++) { g_psum[pb + j] = s[j]; g_psumsq[pb + j] = q[j]; }
}

__global__ void col_stats_finalize(const float* __restrict__ gamma, const float* __restrict__ bnb,
                                   float* __restrict__ scale, float* __restrict__ shift, int C) {
    int c = blockIdx.x * 256 + threadIdx.x;
    double s = 0, q = 0;
    for (int i = 0; i < RSX; i++) { s += (double)g_psum[(size_t)i * C + c]; q += (double)g_psumsq[(size_t)i * C + c]; }
    double mu  = s * (1.0 / NROWS);
    double var = q * (1.0 / NROWS) - mu * mu;
    float a = rsqrtf((float)var + 1e-5f) * gamma[c];
    scale[c] = a;
    shift[c] = bnb[c] - (float)mu * a;
}

__global__ void fold_split(const float* __restrict__ W, const float* __restrict__ bias,
                           const float* __restrict__ scale, const float* __restrict__ shift,
                           __half* __restrict__ Wh, float* __restrict__ bf, int K) {
    int j = blockIdx.x;
    const float* Wr = W + (size_t)j * K;
    float dot = 0.f;
    for (int k = threadIdx.x; k < K; k += 256) {
        float w = Wr[k];
        Wh[(size_t)j * K + k] = __float2half(w * scale[k]);
        dot += w * shift[k];
    }
    __shared__ float red[256];
    red[threadIdx.x] = dot;
    __syncthreads();
    for (int s = 128; s > 0; s >>= 1) {
        if (threadIdx.x < s) red[threadIdx.x] += red[threadIdx.x + s];
        __syncthreads();
    }
    if (threadIdx.x == 0) bf[j] = bias[j] + red[0];
}

// ---------------- mma.sync GEMM: C = A[M,K] @ B[N,K]^T  (fp16, single-pass) ----------------
template <bool L2E>
__global__ __launch_bounds__(256, 2)
void gemm_mma(const __half* __restrict__ A, const __half* __restrict__ B,
              const float* __restrict__ bias, const float* __restrict__ Y,
              const float* __restrict__ betap, float* __restrict__ Cout,
              __half* __restrict__ Ch, int K, int Nout) {
    extern __shared__ __align__(1024) char smem[];
    const uint32_t sb = smem_u32(smem);
    const int tid  = threadIdx.x;
    const int wid  = tid >> 5;
    const int lane = tid & 31;
    const int wm   = (wid >> 2) * 64;      // warp m offset in tile
    const int wn   = (wid & 3) * 32;       // warp n offset in tile

    const int ldb = K * 2;  // row stride, bytes
    const char* gA = (const char*)(A + (size_t)(blockIdx.y * BM) * K);
    const char* gB = (const char*)(B + (size_t)(blockIdx.x * BN) * K);
    const int NC = K / BKC;

    // loader: per stage, A = 128x128B (1024 chunks) + B same; 4 chunks each per thread
    const int lr = tid >> 3;          // 0..31 (row step 1, 4 passes of 32 rows... r = o>>3)
    const int lc = tid & 7;           // chunk col 0..7
    auto load_stage = [&](int ch, uint32_t s0) {
        size_t kb = (size_t)ch * 128; // 64 halves = 128 bytes
#pragma unroll
        for (int t = 0; t < 4; t++) {
            int r = lr + t * 32;
            uint32_t so = (uint32_t)r * 128 + (uint32_t)((lc ^ (r & 7)) << 4);
            size_t go = (size_t)r * ldb + kb + lc * 16;
            cp16(s0 + so,         gA + go);
            cp16(s0 + 16384 + so, gB + go);
        }
    };

    float acc[4][4][4];
#pragma unroll
    for (int i = 0; i < 4; i++)
#pragma unroll
        for (int j = 0; j < 4; j++)
#pragma unroll
            for (int r = 0; r < 4; r++) acc[i][r][0] = acc[i][r][0]; // no-op guard
#pragma unroll
    for (int i = 0; i < 4; i++)
#pragma unroll
        for (int j = 0; j < 4; j++)
#pragma unroll
            for (int r = 0; r < 4; r++) acc[i][j][r] = 0.f;

    // hoisted fragment row bases (per-warp invariant)
    const int ar  = wm + (lane & 15);          // A row for this lane's frags
    const int arx = ar & 7;
    const int br  = wn + (lane & 7) + ((lane & 16) ? 8 : 0);  // B row
    const int brx = br & 7;
    const int ahalf = (lane >> 4);             // chunk parity for A
    const int bhalf = ((lane >> 3) & 1);       // chunk parity for B

    // prologue: fill NSTAGE-1 stages
#pragma unroll
    for (int s = 0; s < NSTAGE - 1; s++) { load_stage(s, sb + s * STAGE); cp_commit(); }

    uint32_t comp_off = 0;
    uint32_t load_off = (NSTAGE - 1) * STAGE;

    for (int i = 0; i < NC; i++) {
        cp_wait1();
        __syncthreads();
        if (i + NSTAGE - 1 < NC) load_stage(i + NSTAGE - 1, sb + load_off);
        cp_commit();
        load_off += STAGE; if (load_off == NSTAGE * STAGE) load_off = 0;

        const uint32_t sA = sb + comp_off, sB = sA + 16384;
        comp_off += STAGE; if (comp_off == NSTAGE * STAGE) comp_off = 0;

#pragma unroll
        for (int kk = 0; kk < 4; kk++) {       // 4 x k16 per BKC=64
            uint32_t ah[4][4], bh[2][4];
            const int ac = kk * 2 + ahalf;
            const int bc = kk * 2 + bhalf;
#pragma unroll
            for (int mi = 0; mi < 4; mi++) {
                const int r = ar + mi * 16;
                ldsm_x4(ah[mi][0], ah[mi][1], ah[mi][2], ah[mi][3],
                        sA + r * 128 + ((ac ^ arx) << 4));
            }
#pragma unroll
            for (int nj = 0; nj < 2; nj++) {
                const int r = br + nj * 16;
                ldsm_x4(bh[nj][0], bh[nj][1], bh[nj][2], bh[nj][3],
                        sB + r * 128 + ((bc ^ brx) << 4));
            }
#pragma unroll
            for (int mi = 0; mi < 4; mi++)
#pragma unroll
                for (int jj = 0; jj < 4; jj++)
                    mma16816(acc[mi][jj], ah[mi], bh[jj >> 1][(jj & 1) * 2], bh[jj >> 1][(jj & 1) * 2 + 1]);
        }
    }
    cp_wait0();

    // ---- epilogue ----
    const int bm_ = blockIdx.y * BM, bn_ = blockIdx.x * BN;
    const float bsc = L2E ? __ldg(betap) : 0.f;
#pragma unroll
    for (int mi = 0; mi < 4; mi++) {
#pragma unroll
        for (int jj = 0; jj < 4; jj++) {
            const int row0 = bm_ + wm + mi * 16 + (lane >> 2);
            const int col  = bn_ + wn + jj * 8 + 2 * (lane & 3);
            const float bb0 = __ldg(&bias[col]), bb1 = __ldg(&bias[col + 1]);
#pragma unroll
            for (int h = 0; h < 2; h++) {
                const int row = row0 + h * 8;
                float v0 = acc[mi][jj][h * 2 + 0] + bb0;
                float v1 = acc[mi][jj][h * 2 + 1] + bb1;
                if (!L2E) {
                    v0 = fmaxf(v0, 0.f); v1 = fmaxf(v1, 0.f);
                    __half2 hv = __halves2half2(__float2half(v0), __float2half(v1));
                    *(__half2*)(Ch + (size_t)row * Nout + col) = hv;
                } else {
                    const float2 yv = *(const float2*)(Y + (size_t)row * Nout + col);
                    float2 o;
                    o.x = v0 + bsc * yv.x;
                    o.y = v1 + bsc * yv.y;
                    *(float2*)(Cout + (size_t)row * Nout + col) = o;
                }
            }
        }
    }
}

// ---------------- launch ----------------
extern "C" void kernel_launch(void* const* d_in, const int* in_sizes, int n_in,
                              void* d_out, int out_size) {
    const float* x    = (const float*)d_in[0];
    const float* y    = (const float*)d_in[1];
    const float* W1   = (const float*)d_in[2];
    const float* b1   = (const float*)d_in[3];
    const float* W2   = (const float*)d_in[4];
    const float* b2   = (const float*)d_in[5];
    const float* bn1g = (const float*)d_in[6];
    const float* bn1b = (const float*)d_in[7];
    const float* bn2g = (const float*)d_in[8];
    const float* bn2b = (const float*)d_in[9];
    const float* beta = (const float*)d_in[10];
    float* out = (float*)d_out;

    __half *xh, *h1, *w1h, *w2h;
    float *b1f, *b2f, *sc1, *sh1, *sc2, *sh2;
    cudaGetSymbolAddress((void**)&xh,  g_xh);
    cudaGetSymbolAddress((void**)&h1,  g_h1);
    cudaGetSymbolAddress((void**)&w1h, g_w1h);
    cudaGetSymbolAddress((void**)&w2h, g_w2h);
    cudaGetSymbolAddress((void**)&b1f, g_b1f);
    cudaGetSymbolAddress((void**)&b2f, g_b2f);
    cudaGetSymbolAddress((void**)&sc1, g_scale1);
    cudaGetSymbolAddress((void**)&sh1, g_shift1);
    cudaGetSymbolAddress((void**)&sc2, g_scale2);
    cudaGetSymbolAddress((void**)&sh2, g_shift2);

    cudaFuncSetAttribute(gemm_mma<false>, cudaFuncAttributeMaxDynamicSharedMemorySize, SMEM_DYN);
    cudaFuncSetAttribute(gemm_mma<true>,  cudaFuncAttributeMaxDynamicSharedMemorySize, SMEM_DYN);

    // layer 1
    conv_stats_x<<<dim3(NFEAT / 1024, RSX), 256>>>(x, xh, NFEAT, NROWS / RSX);
    col_stats_finalize<<<NFEAT / 256, 256>>>(bn1g, bn1b, sc1, sh1, NFEAT);
    fold_split<<<NHID, 256>>>(W1, b1, sc1, sh1, w1h, b1f, NFEAT);
    gemm_mma<false><<<dim3(NHID / BN, NROWS / BM), 256, SMEM_DYN>>>(
        xh, w1h, b1f, nullptr, nullptr, nullptr, h1, NFEAT, NHID);

    // layer 2
    stats_h<<<dim3(NHID / 2048, RSX), 256>>>(h1, NHID, NROWS / RSX);
    col_stats_finalize<<<NHID / 256, 256>>>(bn2g, bn2b, sc2, sh2, NHID);
    fold_split<<<NCLS, 256>>>(W2, b2, sc2, sh2, w2h, b2f, NHID);
    gemm_mma<true><<<dim3(NCLS / BN, NROWS / BM), 256, SMEM_DYN>>>(
        h1, w2h, b2f, y, beta, out, nullptr, NHID, NCLS);
}